// round 1
// baseline (speedup 1.0000x reference)
#include <cuda_runtime.h>
#include <math.h>

#define CF   1984
#define NB   8
#define NN   1024    // h*w = 32*32
#define NCLS 1000

// ---------------- scratch (static device globals; no allocation) ----------------
__device__ float g_tn[NB * NN * CF];        // normalized t  (65 MB)
__device__ float g_rn[NB * NN * CF];        // normalized r  (65 MB)
__device__ float g_A[NB * NN * NN];         // softmax(C)    (33.5 MB)
__device__ float g_frab1[NB * 64 * 64 * 64];
__device__ float g_frab2[NB * NN * 128];
__device__ float g_fa[NB * NN * 128];
__device__ float g_mp[NB * CF];
__device__ float g_g1[NB * 512];

// ---------------- row L2-normalize: out = in / (||in|| + 1e-6) ----------------
__global__ void normalize_rows(const float* __restrict__ in, float* __restrict__ out) {
    int row = blockIdx.x;                       // b*NN + n
    const float* src = in + (size_t)row * CF;
    float* dst = out + (size_t)row * CF;
    float ss = 0.f;
    for (int c = threadIdx.x; c < CF; c += blockDim.x) { float v = src[c]; ss += v * v; }
    __shared__ float red[256];
    red[threadIdx.x] = ss; __syncthreads();
    for (int s = 128; s > 0; s >>= 1) {
        if (threadIdx.x < s) red[threadIdx.x] += red[threadIdx.x + s];
        __syncthreads();
    }
    float inv = 1.f / (sqrtf(red[0]) + 1e-6f);
    for (int c = threadIdx.x; c < CF; c += blockDim.x) dst[c] = src[c] * inv;
}

// ---------------- NT SGEMM: C[M,Nn] = A[M,K] * B[Nn,K]^T (both K-major) ----------------
#define GBM 128
#define GBN 128
#define GBK 8
__global__ __launch_bounds__(256) void gemm_nt(
    const float* __restrict__ Ag, const float* __restrict__ Bg, float* __restrict__ Cg,
    int M, int Nn, int K)
{
    int b = blockIdx.z;
    const float* A = Ag + (size_t)b * M * K;
    const float* B = Bg + (size_t)b * Nn * K;
    float* C = Cg + (size_t)b * M * Nn;

    __shared__ float As[GBK][GBM];
    __shared__ float Bs[GBK][GBN];

    int tid = threadIdx.x;                  // 256 threads
    int row0 = blockIdx.y * GBM;
    int col0 = blockIdx.x * GBN;
    int tx = tid & 15, ty = tid >> 4;       // 16x16, 8x8 micro-tile

    int lr = tid >> 1;                      // load row 0..127
    int lk = (tid & 1) * 4;                 // k offset 0/4

    float acc[8][8];
#pragma unroll
    for (int i = 0; i < 8; i++)
#pragma unroll
        for (int j = 0; j < 8; j++) acc[i][j] = 0.f;

    for (int k0 = 0; k0 < K; k0 += GBK) {
        float4 av = *(const float4*)(A + (size_t)(row0 + lr) * K + k0 + lk);
        float4 bv = *(const float4*)(B + (size_t)(col0 + lr) * K + k0 + lk);
        As[lk + 0][lr] = av.x; As[lk + 1][lr] = av.y; As[lk + 2][lr] = av.z; As[lk + 3][lr] = av.w;
        Bs[lk + 0][lr] = bv.x; Bs[lk + 1][lr] = bv.y; Bs[lk + 2][lr] = bv.z; Bs[lk + 3][lr] = bv.w;
        __syncthreads();
#pragma unroll
        for (int k = 0; k < GBK; k++) {
            float ar[8], br[8];
#pragma unroll
            for (int i = 0; i < 8; i++) ar[i] = As[k][ty * 8 + i];
#pragma unroll
            for (int j = 0; j < 8; j++) br[j] = Bs[k][tx * 8 + j];
#pragma unroll
            for (int i = 0; i < 8; i++)
#pragma unroll
                for (int j = 0; j < 8; j++) acc[i][j] += ar[i] * br[j];
        }
        __syncthreads();
    }
#pragma unroll
    for (int i = 0; i < 8; i++) {
        float* crow = C + (size_t)(row0 + ty * 8 + i) * Nn + col0 + tx * 8;
#pragma unroll
        for (int j = 0; j < 8; j++) crow[j] = acc[i][j];
    }
}

// ---------------- row softmax over NN=1024 ----------------
__global__ void softmax_rows(const float* __restrict__ Cmat, float* __restrict__ Amat) {
    int row = blockIdx.x;
    const float* src = Cmat + (size_t)row * NN;
    float* dst = Amat + (size_t)row * NN;
    int tid = threadIdx.x;                  // 256
    float v[4];
    float m = -1e30f;
#pragma unroll
    for (int i = 0; i < 4; i++) { v[i] = src[tid + i * 256]; m = fmaxf(m, v[i]); }
    __shared__ float red[256];
    red[tid] = m; __syncthreads();
    for (int s = 128; s > 0; s >>= 1) { if (tid < s) red[tid] = fmaxf(red[tid], red[tid + s]); __syncthreads(); }
    m = red[0]; __syncthreads();
    float ssum = 0.f;
#pragma unroll
    for (int i = 0; i < 4; i++) { v[i] = __expf(v[i] - m); ssum += v[i]; }
    red[tid] = ssum; __syncthreads();
    for (int s = 128; s > 0; s >>= 1) { if (tid < s) red[tid] += red[tid + s]; __syncthreads(); }
    float inv = 1.f / red[0];
#pragma unroll
    for (int i = 0; i < 4; i++) dst[tid + i * 256] = v[i] * inv;
}

// ---------------- NN SGEMM: C[M,Nc] = A[M,K] * B[K,Nc], Nc==128 ----------------
#define HBM 64
#define HBK 8
#define HBN 128
__global__ __launch_bounds__(256) void gemm_nn(
    const float* __restrict__ Ag, const float* __restrict__ Bg, float* __restrict__ Cg,
    int M, int Nc, int K)
{
    int b = blockIdx.z;
    const float* A = Ag + (size_t)b * M * K;
    const float* B = Bg + (size_t)b * K * Nc;
    float* C = Cg + (size_t)b * M * Nc;
    int row0 = blockIdx.y * HBM;

    __shared__ float As[HBK][HBM];
    __shared__ float Bs[HBK][HBN];
    int tid = threadIdx.x;                  // 256
    int tx = tid & 15, ty = tid >> 4;       // TM=4 rows, TN=8 cols
    float acc[4][8];
#pragma unroll
    for (int i = 0; i < 4; i++)
#pragma unroll
        for (int j = 0; j < 8; j++) acc[i][j] = 0.f;

    for (int k0 = 0; k0 < K; k0 += HBK) {
        for (int i = tid; i < HBM * HBK; i += 256) {
            int r = i >> 3, k = i & 7;
            As[k][r] = A[(size_t)(row0 + r) * K + k0 + k];
        }
        {
            int r = tid >> 5, c = (tid & 31) * 4;
            float4 bv = *(const float4*)(B + (size_t)(k0 + r) * Nc + c);
            Bs[r][c] = bv.x; Bs[r][c + 1] = bv.y; Bs[r][c + 2] = bv.z; Bs[r][c + 3] = bv.w;
        }
        __syncthreads();
#pragma unroll
        for (int k = 0; k < HBK; k++) {
            float ar[4], br[8];
#pragma unroll
            for (int i = 0; i < 4; i++) ar[i] = As[k][ty * 4 + i];
#pragma unroll
            for (int j = 0; j < 8; j++) br[j] = Bs[k][tx * 8 + j];
#pragma unroll
            for (int i = 0; i < 4; i++)
#pragma unroll
                for (int j = 0; j < 8; j++) acc[i][j] += ar[i] * br[j];
        }
        __syncthreads();
    }
#pragma unroll
    for (int i = 0; i < 4; i++) {
        float* crow = C + (size_t)(row0 + ty * 4 + i) * Nc + tx * 8;
#pragma unroll
        for (int j = 0; j < 8; j++) crow[j] = acc[i][j];
    }
}

// ---------------- direct 3x3 conv + bias + relu, NHWC, blockDim.x == Cout ----------------
template <int TILE, int STRIDE>
__global__ void conv2d_relu_k(
    const float* __restrict__ in, const float* __restrict__ w,
    const float* __restrict__ bias, float* __restrict__ out,
    int Hin, int Win, int Cin, int Hout, int Wout, int Cout, int pad)
{
    constexpr int SPANX = (TILE - 1) * STRIDE + 3;
    extern __shared__ float sm[];           // [3][SPANX][Cin]
    int b = blockIdx.z;
    int oy = blockIdx.y;
    int ox0 = blockIdx.x * TILE;
    int co = threadIdx.x;

    int iy0 = oy * STRIDE - pad;
    int ix0 = ox0 * STRIDE - pad;
    int tot = 3 * SPANX * Cin;
    for (int i = threadIdx.x; i < tot; i += blockDim.x) {
        int ci = i % Cin; int rest = i / Cin;
        int xx = rest % SPANX; int r = rest / SPANX;
        int iy = iy0 + r, ix = ix0 + xx;
        float v = 0.f;
        if (iy >= 0 && iy < Hin && ix >= 0 && ix < Win)
            v = in[(((size_t)b * Hin + iy) * Win + ix) * Cin + ci];
        sm[(r * SPANX + xx) * Cin + ci] = v;
    }
    __syncthreads();

    float acc[TILE];
    float bv = bias[co];
#pragma unroll
    for (int p = 0; p < TILE; p++) acc[p] = bv;

    for (int r = 0; r < 3; r++)
        for (int kx = 0; kx < 3; kx++)
            for (int ci = 0; ci < Cin; ci++) {
                float wv = w[(size_t)((r * 3 + kx) * Cin + ci) * Cout + co];
                const float* srow = &sm[(r * SPANX + kx) * Cin + ci];
#pragma unroll
                for (int p = 0; p < TILE; p++)
                    acc[p] += srow[(size_t)p * STRIDE * Cin] * wv;
            }
#pragma unroll
    for (int p = 0; p < TILE; p++) {
        int ox = ox0 + p;
        out[(((size_t)b * Hout + oy) * Wout + ox) * Cout + co] = fmaxf(acc[p], 0.f);
    }
}

// ---------------- global max-pool over N positions ----------------
__global__ void maxpool_k(const float* __restrict__ t, float* __restrict__ mp) {
    int b = blockIdx.y;
    int c = blockIdx.x * blockDim.x + threadIdx.x;
    if (c >= CF) return;
    const float* src = t + (size_t)b * NN * CF + c;
    float m = -1e30f;
    for (int n = 0; n < NN; n++) m = fmaxf(m, src[(size_t)n * CF]);
    mp[b * CF + c] = m;
}

// ---------------- dense1: relu(mp @ w_d1 + b_d1), [8,1984]x[1984,512] ----------------
__global__ void dense1_k(const float* __restrict__ mp, const float* __restrict__ w,
                         const float* __restrict__ bias, float* __restrict__ g1) {
    int b = blockIdx.x; int j = threadIdx.x;     // 512
    __shared__ float sm[CF];
    for (int k = threadIdx.x; k < CF; k += blockDim.x) sm[k] = mp[b * CF + k];
    __syncthreads();
    float s = bias[j];
    for (int k = 0; k < CF; k++) s += sm[k] * w[(size_t)k * 512 + j];
    g1[b * 512 + j] = fmaxf(s, 0.f);
}

// ---------------- dense2 + softmax: softmax(g1 @ w_d2 + b_d2) ----------------
__global__ void dense2_softmax_k(const float* __restrict__ g1, const float* __restrict__ w,
                                 const float* __restrict__ bias, float* __restrict__ out) {
    int b = blockIdx.x;
    __shared__ float sg[512];
    __shared__ float logits[NCLS];
    __shared__ float red[256];
    int tid = threadIdx.x;                       // 256
    for (int k = tid; k < 512; k += 256) sg[k] = g1[b * 512 + k];
    __syncthreads();
    for (int j = tid; j < NCLS; j += 256) {
        float s = bias[j];
        for (int k = 0; k < 512; k++) s += sg[k] * w[(size_t)k * NCLS + j];
        logits[j] = s;
    }
    __syncthreads();
    float m = -1e30f;
    for (int j = tid; j < NCLS; j += 256) m = fmaxf(m, logits[j]);
    red[tid] = m; __syncthreads();
    for (int s = 128; s > 0; s >>= 1) { if (tid < s) red[tid] = fmaxf(red[tid], red[tid + s]); __syncthreads(); }
    m = red[0]; __syncthreads();
    float ssum = 0.f;
    for (int j = tid; j < NCLS; j += 256) { float e = __expf(logits[j] - m); logits[j] = e; ssum += e; }
    red[tid] = ssum; __syncthreads();
    for (int s = 128; s > 0; s >>= 1) { if (tid < s) red[tid] += red[tid + s]; __syncthreads(); }
    float inv = 1.f / red[0];
    for (int j = tid; j < NCLS; j += 256) out[b * NCLS + j] = logits[j] * inv;
}

// ---------------- launcher ----------------
extern "C" void kernel_launch(void* const* d_in, const int* in_sizes, int n_in,
                              void* d_out, int out_size) {
    const float* t_lum  = (const float*)d_in[0];
    const float* r_lum  = (const float*)d_in[1];
    const float* r_ab   = (const float*)d_in[2];
    const float* w_rab1 = (const float*)d_in[3];
    const float* b_rab1 = (const float*)d_in[4];
    const float* w_rab2 = (const float*)d_in[5];
    const float* b_rab2 = (const float*)d_in[6];
    const float* w_fa1  = (const float*)d_in[7];
    const float* b_fa1  = (const float*)d_in[8];
    const float* w_fa2  = (const float*)d_in[9];
    const float* b_fa2  = (const float*)d_in[10];
    const float* w_fa3  = (const float*)d_in[11];
    const float* b_fa3  = (const float*)d_in[12];
    const float* w_d1   = (const float*)d_in[13];
    const float* b_d1   = (const float*)d_in[14];
    const float* w_d2   = (const float*)d_in[15];
    const float* b_d2   = (const float*)d_in[16];

    float *tn, *rn, *Amat, *frab1, *frab2, *fa, *mp, *g1;
    cudaGetSymbolAddress((void**)&tn,    g_tn);
    cudaGetSymbolAddress((void**)&rn,    g_rn);
    cudaGetSymbolAddress((void**)&Amat,  g_A);
    cudaGetSymbolAddress((void**)&frab1, g_frab1);
    cudaGetSymbolAddress((void**)&frab2, g_frab2);
    cudaGetSymbolAddress((void**)&fa,    g_fa);
    cudaGetSymbolAddress((void**)&mp,    g_mp);
    cudaGetSymbolAddress((void**)&g1,    g_g1);

    float* out  = (float*)d_out;
    float* Cmat = out + 8000;          // [8,1024,1024]
    float* s1   = out + 8396608;       // [8,4,4,512]
    float* s2   = out + 8462144;       // [8,8,8,256]
    float* s3   = out + 8593216;       // [8,16,16,128]

    // normalize both feature stacks
    normalize_rows<<<NB * NN, 256>>>(t_lum, tn);
    normalize_rows<<<NB * NN, 256>>>(r_lum, rn);

    // cost volume C = tn @ rn^T (dominant GEMM)
    gemm_nt<<<dim3(NN / GBN, NN / GBM, NB), 256>>>(tn, rn, Cmat, NN, NN, CF);

    // chroma branch (independent of C; overlaps in-graph)
    conv2d_relu_k<16, 1><<<dim3(64 / 16, 64, NB), 64, 3 * 18 * 2 * 4>>>(
        r_ab, w_rab1, b_rab1, frab1, 64, 64, 2, 64, 64, 64, 1);
    conv2d_relu_k<16, 2><<<dim3(32 / 16, 32, NB), 128, 3 * 33 * 64 * 4>>>(
        frab1, w_rab2, b_rab2, frab2, 64, 64, 64, 32, 32, 128, 0);

    // attention
    softmax_rows<<<NB * NN, 256>>>(Cmat, Amat);
    gemm_nn<<<dim3(1, NN / HBM, NB), 256>>>(Amat, frab2, fa, NN, 128, NN);

    // pyramid
    conv2d_relu_k<8, 2><<<dim3(16 / 8, 16, NB), 128, 3 * 17 * 128 * 4>>>(
        fa, w_fa1, b_fa1, s3, 32, 32, 128, 16, 16, 128, 0);
    conv2d_relu_k<8, 2><<<dim3(8 / 8, 8, NB), 256, 3 * 17 * 128 * 4>>>(
        s3, w_fa2, b_fa2, s2, 16, 16, 128, 8, 8, 256, 0);
    conv2d_relu_k<4, 2><<<dim3(4 / 4, 4, NB), 512, 3 * 9 * 256 * 4>>>(
        s2, w_fa3, b_fa3, s1, 8, 8, 256, 4, 4, 512, 0);

    // classifier head
    maxpool_k<<<dim3((CF + 255) / 256, NB), 256>>>(t_lum, mp);
    dense1_k<<<NB, 512>>>(mp, w_d1, b_d1, g1);
    dense2_softmax_k<<<NB, 256>>>(g1, w_d2, b_d2, out);
}

// round 5
// speedup vs baseline: 1.2237x; 1.2237x over previous
#include <cuda_runtime.h>
#include <cuda_bf16.h>
#include <math.h>
#include <stdint.h>

#define CF   1984
#define NB   8
#define NN   1024    // h*w = 32*32
#define NCLS 1000

// ---------------- scratch (static device globals; no allocation) ----------------
__device__ __nv_bfloat16 g_tn_hi[NB * NN * CF];
__device__ __nv_bfloat16 g_tn_lo[NB * NN * CF];
__device__ __nv_bfloat16 g_rn_hi[NB * NN * CF];
__device__ __nv_bfloat16 g_rn_lo[NB * NN * CF];
__device__ float g_A[NB * NN * NN];         // softmax(C)
__device__ float g_frab1[NB * 64 * 64 * 64];
__device__ float g_frab2[NB * NN * 128];
__device__ float g_fa[NB * NN * 128];
__device__ float g_mp[NB * CF];
__device__ float g_g1[NB * 512];

// ============================ helpers ============================
__device__ __forceinline__ uint32_t smem_u32(const void* p) {
    uint32_t a;
    asm("{ .reg .u64 t; cvta.to.shared.u64 t, %1; cvt.u32.u64 %0, t; }" : "=r"(a) : "l"(p));
    return a;
}
__device__ __forceinline__ void cp_async16(uint32_t dst, const void* src) {
    asm volatile("cp.async.cg.shared.global [%0], [%1], 16;" :: "r"(dst), "l"(src));
}
#define CP_COMMIT() asm volatile("cp.async.commit_group;" ::: "memory")
#define CP_WAIT(n)  asm volatile("cp.async.wait_group %0;" :: "n"(n) : "memory")

__device__ __forceinline__ void ldsm_x4(uint32_t* r, uint32_t addr) {
    asm volatile("ldmatrix.sync.aligned.m8n8.x4.shared.b16 {%0,%1,%2,%3}, [%4];"
                 : "=r"(r[0]), "=r"(r[1]), "=r"(r[2]), "=r"(r[3]) : "r"(addr));
}
__device__ __forceinline__ void mma16816(float* d, const uint32_t* a, const uint32_t* b) {
    asm volatile(
        "mma.sync.aligned.m16n8k16.row.col.f32.bf16.bf16.f32 "
        "{%0,%1,%2,%3}, {%4,%5,%6,%7}, {%8,%9}, {%0,%1,%2,%3};"
        : "+f"(d[0]), "+f"(d[1]), "+f"(d[2]), "+f"(d[3])
        : "r"(a[0]), "r"(a[1]), "r"(a[2]), "r"(a[3]), "r"(b[0]), "r"(b[1]));
}

// ---------------- normalize + bf16 hi/lo split ----------------
__global__ void normalize_split(const float* __restrict__ in,
                                __nv_bfloat16* __restrict__ hi,
                                __nv_bfloat16* __restrict__ lo) {
    int row = blockIdx.x;
    const float* src = in + (size_t)row * CF;
    __nv_bfloat16* dh = hi + (size_t)row * CF;
    __nv_bfloat16* dl = lo + (size_t)row * CF;
    float ss = 0.f;
    for (int c = threadIdx.x; c < CF; c += blockDim.x) { float v = src[c]; ss += v * v; }
    __shared__ float red[256];
    red[threadIdx.x] = ss; __syncthreads();
    for (int s = 128; s > 0; s >>= 1) {
        if (threadIdx.x < s) red[threadIdx.x] += red[threadIdx.x + s];
        __syncthreads();
    }
    float inv = 1.f / (sqrtf(red[0]) + 1e-6f);
    for (int c = threadIdx.x; c < CF; c += blockDim.x) {
        float x = src[c] * inv;
        __nv_bfloat16 h = __float2bfloat16(x);
        dh[c] = h;
        dl[c] = __float2bfloat16(x - __bfloat162float(h));
    }
}

// ---------------- mma.sync bf16 NT GEMM with split-bf16 fp32 emulation ----------------
// C[1024,1024] = Ahi*Bhi^T + Alo*Bhi^T + Ahi*Blo^T   (phase-scheduled K' = 3*1984)
// CTA 128x128, warp 64x32 (2x4 warps), K-chunk 32, 3-stage cp.async pipeline.
#define KCH    32
#define CHPP   (CF / KCH)      // 62 chunks per phase
#define NCH    (3 * CHPP)      // 186
#define PIPE   3
#define SAST   40              // SMEM row stride in bf16 elems (80B) - conflict-free for ldmatrix
#define TILEB  (128 * SAST * 2)   // 10240 B
#define STAGEB (2 * TILEB)        // 20480 B (A tile + B tile)
#define GSMEM  (PIPE * STAGEB)    // 61440 B

__global__ __launch_bounds__(256) void gemm_nt_mma(
    const __nv_bfloat16* __restrict__ Ahi, const __nv_bfloat16* __restrict__ Alo,
    const __nv_bfloat16* __restrict__ Bhi, const __nv_bfloat16* __restrict__ Blo,
    float* __restrict__ Cg)
{
    extern __shared__ __align__(128) char smem[];
    uint32_t sbase = smem_u32(smem);
    int tid = threadIdx.x;
    int wid = tid >> 5, lane = tid & 31;
    int warp_m = wid & 1;          // 0..1  -> 64 rows
    int warp_n = wid >> 1;         // 0..3  -> 32 cols

    int b = blockIdx.z;
    int row0 = blockIdx.y * 128;
    int col0 = blockIdx.x * 128;

    const __nv_bfloat16* Apl[3] = {
        Ahi + ((size_t)b * NN + row0) * CF,
        Alo + ((size_t)b * NN + row0) * CF,
        Ahi + ((size_t)b * NN + row0) * CF };
    const __nv_bfloat16* Bpl[3] = {
        Bhi + ((size_t)b * NN + col0) * CF,
        Bhi + ((size_t)b * NN + col0) * CF,
        Blo + ((size_t)b * NN + col0) * CF };
    float* C = Cg + (size_t)b * NN * NN;

    float acc[4][4][4];
#pragma unroll
    for (int i = 0; i < 4; i++)
#pragma unroll
        for (int j = 0; j < 4; j++)
#pragma unroll
            for (int k = 0; k < 4; k++) acc[i][j][k] = 0.f;

    // prefetch lambda: chunk c -> stage c%PIPE
    auto prefetch = [&](int c) {
        int ph = c / CHPP;
        int kk = (c % CHPP) * KCH;
        const __nv_bfloat16* As = Apl[ph] + kk;
        const __nv_bfloat16* Bs = Bpl[ph] + kk;
        uint32_t stg = sbase + (c % PIPE) * STAGEB;
#pragma unroll
        for (int it = 0; it < 2; it++) {
            int idx = it * 256 + tid;      // 0..511
            int r = idx >> 2, seg = idx & 3;
            uint32_t off = (uint32_t)(r * (SAST * 2) + seg * 16);
            cp_async16(stg + off,          As + (size_t)r * CF + seg * 8);
            cp_async16(stg + TILEB + off,  Bs + (size_t)r * CF + seg * 8);
        }
    };

    prefetch(0); CP_COMMIT();
    prefetch(1); CP_COMMIT();

    // ldmatrix lane addressing precompute
    int a_row = (lane & 7) + ((lane >> 3) & 1) * 8;   // row within 16 (tile pattern)
    int a_k8  = (lane >> 4) * 8;                      // +8 k for tiles 2,3
    int bg    = lane >> 3;                            // group 0..3
    int b_nat = bg >> 1;                              // n-atom within pair
    int b_k8  = (bg & 1) * 8;

    for (int c = 0; c < NCH; c++) {
        CP_WAIT(PIPE - 2);
        __syncthreads();
        if (c + PIPE - 1 < NCH) prefetch(c + PIPE - 1);
        CP_COMMIT();

        uint32_t sA = sbase + (c % PIPE) * STAGEB;
        uint32_t sB = sA + TILEB;
#pragma unroll
        for (int k16 = 0; k16 < 2; k16++) {
            int kb = k16 * 16;
            uint32_t af[4][4];
#pragma unroll
            for (int am = 0; am < 4; am++) {
                uint32_t ad = sA + (uint32_t)((warp_m * 64 + am * 16 + a_row) * (SAST * 2)
                                              + (kb + a_k8) * 2);
                ldsm_x4(af[am], ad);
            }
            uint32_t bf[4][2];
#pragma unroll
            for (int bp = 0; bp < 2; bp++) {
                uint32_t r[4];
                uint32_t bd = sB + (uint32_t)((warp_n * 32 + (bp * 2 + b_nat) * 8 + (lane & 7)) * (SAST * 2)
                                              + (kb + b_k8) * 2);
                ldsm_x4(r, bd);
                bf[bp * 2 + 0][0] = r[0]; bf[bp * 2 + 0][1] = r[1];
                bf[bp * 2 + 1][0] = r[2]; bf[bp * 2 + 1][1] = r[3];
            }
#pragma unroll
            for (int am = 0; am < 4; am++)
#pragma unroll
                for (int an = 0; an < 4; an++)
                    mma16816(acc[am][an], af[am], bf[an]);
        }
        __syncthreads();
    }

    // epilogue
    int tr = lane >> 2, tc = (lane & 3) * 2;
#pragma unroll
    for (int am = 0; am < 4; am++) {
#pragma unroll
        for (int an = 0; an < 4; an++) {
            int r = row0 + warp_m * 64 + am * 16 + tr;
            int cc = col0 + warp_n * 32 + an * 8 + tc;
            float2 v0 = make_float2(acc[am][an][0], acc[am][an][1]);
            float2 v1 = make_float2(acc[am][an][2], acc[am][an][3]);
            *(float2*)(C + (size_t)r * NN + cc) = v0;
            *(float2*)(C + (size_t)(r + 8) * NN + cc) = v1;
        }
    }
}

// ---------------- row softmax over NN=1024 ----------------
__global__ void softmax_rows(const float* __restrict__ Cmat, float* __restrict__ Amat) {
    int row = blockIdx.x;
    const float* src = Cmat + (size_t)row * NN;
    float* dst = Amat + (size_t)row * NN;
    int tid = threadIdx.x;                  // 256
    float v[4];
    float m = -1e30f;
#pragma unroll
    for (int i = 0; i < 4; i++) { v[i] = src[tid + i * 256]; m = fmaxf(m, v[i]); }
    __shared__ float red[256];
    red[tid] = m; __syncthreads();
    for (int s = 128; s > 0; s >>= 1) { if (tid < s) red[tid] = fmaxf(red[tid], red[tid + s]); __syncthreads(); }
    m = red[0]; __syncthreads();
    float ssum = 0.f;
#pragma unroll
    for (int i = 0; i < 4; i++) { v[i] = __expf(v[i] - m); ssum += v[i]; }
    red[tid] = ssum; __syncthreads();
    for (int s = 128; s > 0; s >>= 1) { if (tid < s) red[tid] += red[tid + s]; __syncthreads(); }
    float inv = 1.f / red[0];
#pragma unroll
    for (int i = 0; i < 4; i++) dst[tid + i * 256] = v[i] * inv;
}

// ---------------- NN SGEMM: C[M,Nc] = A[M,K] * B[K,Nc], Nc==128 ----------------
#define HBM 64
#define HBK 8
#define HBN 128
__global__ __launch_bounds__(256) void gemm_nn(
    const float* __restrict__ Ag, const float* __restrict__ Bg, float* __restrict__ Cg,
    int M, int Nc, int K)
{
    int b = blockIdx.z;
    const float* A = Ag + (size_t)b * M * K;
    const float* B = Bg + (size_t)b * K * Nc;
    float* C = Cg + (size_t)b * M * Nc;
    int row0 = blockIdx.y * HBM;

    __shared__ float As[HBK][HBM];
    __shared__ float Bs[HBK][HBN];
    int tid = threadIdx.x;                  // 256
    int tx = tid & 15, ty = tid >> 4;       // TM=4 rows, TN=8 cols
    float acc[4][8];
#pragma unroll
    for (int i = 0; i < 4; i++)
#pragma unroll
        for (int j = 0; j < 8; j++) acc[i][j] = 0.f;

    for (int k0 = 0; k0 < K; k0 += HBK) {
        for (int i = tid; i < HBM * HBK; i += 256) {
            int r = i >> 3, k = i & 7;
            As[k][r] = A[(size_t)(row0 + r) * K + k0 + k];
        }
        {
            int r = tid >> 5, c = (tid & 31) * 4;
            float4 bv = *(const float4*)(B + (size_t)(k0 + r) * Nc + c);
            Bs[r][c] = bv.x; Bs[r][c + 1] = bv.y; Bs[r][c + 2] = bv.z; Bs[r][c + 3] = bv.w;
        }
        __syncthreads();
#pragma unroll
        for (int k = 0; k < HBK; k++) {
            float ar[4], br[8];
#pragma unroll
            for (int i = 0; i < 4; i++) ar[i] = As[k][ty * 4 + i];
#pragma unroll
            for (int j = 0; j < 8; j++) br[j] = Bs[k][tx * 8 + j];
#pragma unroll
            for (int i = 0; i < 4; i++)
#pragma unroll
                for (int j = 0; j < 8; j++) acc[i][j] += ar[i] * br[j];
        }
        __syncthreads();
    }
#pragma unroll
    for (int i = 0; i < 4; i++) {
        float* crow = C + (size_t)(row0 + ty * 4 + i) * Nc + tx * 8;
#pragma unroll
        for (int j = 0; j < 8; j++) crow[j] = acc[i][j];
    }
}

// ---------------- direct 3x3 conv + bias + relu, NHWC, blockDim.x == Cout ----------------
template <int TILE, int STRIDE>
__global__ void conv2d_relu_k(
    const float* __restrict__ in, const float* __restrict__ w,
    const float* __restrict__ bias, float* __restrict__ out,
    int Hin, int Win, int Cin, int Hout, int Wout, int Cout, int pad)
{
    constexpr int SPANX = (TILE - 1) * STRIDE + 3;
    extern __shared__ float sm[];           // [3][SPANX][Cin]
    int b = blockIdx.z;
    int oy = blockIdx.y;
    int ox0 = blockIdx.x * TILE;
    int co = threadIdx.x;

    int iy0 = oy * STRIDE - pad;
    int ix0 = ox0 * STRIDE - pad;
    int tot = 3 * SPANX * Cin;
    for (int i = threadIdx.x; i < tot; i += blockDim.x) {
        int ci = i % Cin; int rest = i / Cin;
        int xx = rest % SPANX; int r = rest / SPANX;
        int iy = iy0 + r, ix = ix0 + xx;
        float v = 0.f;
        if (iy >= 0 && iy < Hin && ix >= 0 && ix < Win)
            v = in[(((size_t)b * Hin + iy) * Win + ix) * Cin + ci];
        sm[(r * SPANX + xx) * Cin + ci] = v;
    }
    __syncthreads();

    float acc[TILE];
    float bv = bias[co];
#pragma unroll
    for (int p = 0; p < TILE; p++) acc[p] = bv;

    for (int r = 0; r < 3; r++)
        for (int kx = 0; kx < 3; kx++)
            for (int ci = 0; ci < Cin; ci++) {
                float wv = w[(size_t)((r * 3 + kx) * Cin + ci) * Cout + co];
                const float* srow = &sm[(r * SPANX + kx) * Cin + ci];
#pragma unroll
                for (int p = 0; p < TILE; p++)
                    acc[p] += srow[(size_t)p * STRIDE * Cin] * wv;
            }
#pragma unroll
    for (int p = 0; p < TILE; p++) {
        int ox = ox0 + p;
        out[(((size_t)b * Hout + oy) * Wout + ox) * Cout + co] = fmaxf(acc[p], 0.f);
    }
}

// ---------------- global max-pool over N positions ----------------
__global__ void maxpool_k(const float* __restrict__ t, float* __restrict__ mp) {
    int b = blockIdx.y;
    int c = blockIdx.x * blockDim.x + threadIdx.x;
    if (c >= CF) return;
    const float* src = t + (size_t)b * NN * CF + c;
    float m = -1e30f;
    for (int n = 0; n < NN; n++) m = fmaxf(m, src[(size_t)n * CF]);
    mp[b * CF + c] = m;
}

// ---------------- dense1: relu(mp @ w_d1 + b_d1) ----------------
__global__ void dense1_k(const float* __restrict__ mp, const float* __restrict__ w,
                         const float* __restrict__ bias, float* __restrict__ g1) {
    int b = blockIdx.x; int j = threadIdx.x;     // 512
    __shared__ float sm[CF];
    for (int k = threadIdx.x; k < CF; k += blockDim.x) sm[k] = mp[b * CF + k];
    __syncthreads();
    float s = bias[j];
    for (int k = 0; k < CF; k++) s += sm[k] * w[(size_t)k * 512 + j];
    g1[b * 512 + j] = fmaxf(s, 0.f);
}

// ---------------- dense2 + softmax ----------------
__global__ void dense2_softmax_k(const float* __restrict__ g1, const float* __restrict__ w,
                                 const float* __restrict__ bias, float* __restrict__ out) {
    int b = blockIdx.x;
    __shared__ float sg[512];
    __shared__ float logits[NCLS];
    __shared__ float red[256];
    int tid = threadIdx.x;                       // 256
    for (int k = tid; k < 512; k += 256) sg[k] = g1[b * 512 + k];
    __syncthreads();
    for (int j = tid; j < NCLS; j += 256) {
        float s = bias[j];
        for (int k = 0; k < 512; k++) s += sg[k] * w[(size_t)k * NCLS + j];
        logits[j] = s;
    }
    __syncthreads();
    float m = -1e30f;
    for (int j = tid; j < NCLS; j += 256) m = fmaxf(m, logits[j]);
    red[tid] = m; __syncthreads();
    for (int s = 128; s > 0; s >>= 1) { if (tid < s) red[tid] = fmaxf(red[tid], red[tid + s]); __syncthreads(); }
    m = red[0]; __syncthreads();
    float ssum = 0.f;
    for (int j = tid; j < NCLS; j += 256) { float e = __expf(logits[j] - m); logits[j] = e; ssum += e; }
    red[tid] = ssum; __syncthreads();
    for (int s = 128; s > 0; s >>= 1) { if (tid < s) red[tid] += red[tid + s]; __syncthreads(); }
    float inv = 1.f / red[0];
    for (int j = tid; j < NCLS; j += 256) out[b * NCLS + j] = logits[j] * inv;
}

// ---------------- launcher ----------------
extern "C" void kernel_launch(void* const* d_in, const int* in_sizes, int n_in,
                              void* d_out, int out_size) {
    const float* t_lum  = (const float*)d_in[0];
    const float* r_lum  = (const float*)d_in[1];
    const float* r_ab   = (const float*)d_in[2];
    const float* w_rab1 = (const float*)d_in[3];
    const float* b_rab1 = (const float*)d_in[4];
    const float* w_rab2 = (const float*)d_in[5];
    const float* b_rab2 = (const float*)d_in[6];
    const float* w_fa1  = (const float*)d_in[7];
    const float* b_fa1  = (const float*)d_in[8];
    const float* w_fa2  = (const float*)d_in[9];
    const float* b_fa2  = (const float*)d_in[10];
    const float* w_fa3  = (const float*)d_in[11];
    const float* b_fa3  = (const float*)d_in[12];
    const float* w_d1   = (const float*)d_in[13];
    const float* b_d1   = (const float*)d_in[14];
    const float* w_d2   = (const float*)d_in[15];
    const float* b_d2   = (const float*)d_in[16];

    __nv_bfloat16 *tnh, *tnl, *rnh, *rnl;
    float *Amat, *frab1, *frab2, *fa, *mp, *g1;
    cudaGetSymbolAddress((void**)&tnh,   g_tn_hi);
    cudaGetSymbolAddress((void**)&tnl,   g_tn_lo);
    cudaGetSymbolAddress((void**)&rnh,   g_rn_hi);
    cudaGetSymbolAddress((void**)&rnl,   g_rn_lo);
    cudaGetSymbolAddress((void**)&Amat,  g_A);
    cudaGetSymbolAddress((void**)&frab1, g_frab1);
    cudaGetSymbolAddress((void**)&frab2, g_frab2);
    cudaGetSymbolAddress((void**)&fa,    g_fa);
    cudaGetSymbolAddress((void**)&mp,    g_mp);
    cudaGetSymbolAddress((void**)&g1,    g_g1);

    cudaFuncSetAttribute(gemm_nt_mma, cudaFuncAttributeMaxDynamicSharedMemorySize, GSMEM);

    float* out  = (float*)d_out;
    float* Cmat = out + 8000;          // [8,1024,1024]
    float* s1   = out + 8396608;       // [8,4,4,512]
    float* s2   = out + 8462144;       // [8,8,8,256]
    float* s3   = out + 8593216;       // [8,16,16,128]

    // normalize + bf16 split
    normalize_split<<<NB * NN, 256>>>(t_lum, tnh, tnl);
    normalize_split<<<NB * NN, 256>>>(r_lum, rnh, rnl);

    // cost volume C = tn @ rn^T on tensor cores (split-bf16, mma.sync)
    gemm_nt_mma<<<dim3(8, 8, NB), 256, GSMEM>>>(tnh, tnl, rnh, rnl, Cmat);

    // chroma branch
    conv2d_relu_k<16, 1><<<dim3(64 / 16, 64, NB), 64, 3 * 18 * 2 * 4>>>(
        r_ab, w_rab1, b_rab1, frab1, 64, 64, 2, 64, 64, 64, 1);
    conv2d_relu_k<16, 2><<<dim3(32 / 16, 32, NB), 128, 3 * 33 * 64 * 4>>>(
        frab1, w_rab2, b_rab2, frab2, 64, 64, 64, 32, 32, 128, 0);

    // attention
    softmax_rows<<<NB * NN, 256>>>(Cmat, Amat);
    gemm_nn<<<dim3(1, NN / HBM, NB), 256>>>(Amat, frab2, fa, NN, 128, NN);

    // pyramid
    conv2d_relu_k<8, 2><<<dim3(16 / 8, 16, NB), 128, 3 * 17 * 128 * 4>>>(
        fa, w_fa1, b_fa1, s3, 32, 32, 128, 16, 16, 128, 0);
    conv2d_relu_k<8, 2><<<dim3(8 / 8, 8, NB), 256, 3 * 17 * 128 * 4>>>(
        s3, w_fa2, b_fa2, s2, 16, 16, 128, 8, 8, 256, 0);
    conv2d_relu_k<4, 2><<<dim3(4 / 4, 4, NB), 512, 3 * 9 * 256 * 4>>>(
        s2, w_fa3, b_fa3, s1, 8, 8, 256, 4, 4, 512, 0);

    // classifier head
    maxpool_k<<<dim3((CF + 255) / 256, NB), 256>>>(t_lum, mp);
    dense1_k<<<NB, 512>>>(mp, w_d1, b_d1, g1);
    dense2_softmax_k<<<NB, 256>>>(g1, w_d2, b_d2, out);
}

// round 6
// speedup vs baseline: 1.4001x; 1.1441x over previous
#include <cuda_runtime.h>
#include <cuda_bf16.h>
#include <math.h>
#include <stdint.h>

#define CF   1984
#define NB   8
#define NN   1024    // h*w = 32*32
#define NCLS 1000

// ---------------- scratch (static device globals; no allocation) ----------------
__device__ __nv_bfloat16 g_tn_hi[NB * NN * CF];
__device__ __nv_bfloat16 g_tn_lo[NB * NN * CF];
__device__ __nv_bfloat16 g_rn_hi[NB * NN * CF];
__device__ __nv_bfloat16 g_rn_lo[NB * NN * CF];
__device__ __nv_bfloat16 g_A_hi[NB * NN * NN];      // softmax(C) hi
__device__ __nv_bfloat16 g_A_lo[NB * NN * NN];      // softmax(C) lo
__device__ __nv_bfloat16 g_frabT_hi[NB * 128 * NN]; // f_rab transposed [b][ch][pos]
__device__ __nv_bfloat16 g_frabT_lo[NB * 128 * NN];
__device__ float g_frab1[NB * 64 * 64 * 64];
__device__ float g_fa[NB * NN * 128];
__device__ float g_mp[NB * CF];
__device__ float g_g1[NB * 512];

// ============================ helpers ============================
__device__ __forceinline__ uint32_t smem_u32(const void* p) {
    uint32_t a;
    asm("{ .reg .u64 t; cvta.to.shared.u64 t, %1; cvt.u32.u64 %0, t; }" : "=r"(a) : "l"(p));
    return a;
}
__device__ __forceinline__ void cp_async16(uint32_t dst, const void* src) {
    asm volatile("cp.async.cg.shared.global [%0], [%1], 16;" :: "r"(dst), "l"(src));
}
#define CP_COMMIT() asm volatile("cp.async.commit_group;" ::: "memory")
#define CP_WAIT(n)  asm volatile("cp.async.wait_group %0;" :: "n"(n) : "memory")

__device__ __forceinline__ void ldsm_x4(uint32_t* r, uint32_t addr) {
    asm volatile("ldmatrix.sync.aligned.m8n8.x4.shared.b16 {%0,%1,%2,%3}, [%4];"
                 : "=r"(r[0]), "=r"(r[1]), "=r"(r[2]), "=r"(r[3]) : "r"(addr));
}
__device__ __forceinline__ void mma16816(float* d, const uint32_t* a, const uint32_t* b) {
    asm volatile(
        "mma.sync.aligned.m16n8k16.row.col.f32.bf16.bf16.f32 "
        "{%0,%1,%2,%3}, {%4,%5,%6,%7}, {%8,%9}, {%0,%1,%2,%3};"
        : "+f"(d[0]), "+f"(d[1]), "+f"(d[2]), "+f"(d[3])
        : "r"(a[0]), "r"(a[1]), "r"(a[2]), "r"(a[3]), "r"(b[0]), "r"(b[1]));
}

// ---------------- normalize + bf16 hi/lo split ----------------
__global__ void normalize_split(const float* __restrict__ in,
                                __nv_bfloat16* __restrict__ hi,
                                __nv_bfloat16* __restrict__ lo) {
    int row = blockIdx.x;
    const float* src = in + (size_t)row * CF;
    __nv_bfloat16* dh = hi + (size_t)row * CF;
    __nv_bfloat16* dl = lo + (size_t)row * CF;
    float ss = 0.f;
    for (int c = threadIdx.x; c < CF; c += blockDim.x) { float v = src[c]; ss += v * v; }
    __shared__ float red[256];
    red[threadIdx.x] = ss; __syncthreads();
    for (int s = 128; s > 0; s >>= 1) {
        if (threadIdx.x < s) red[threadIdx.x] += red[threadIdx.x + s];
        __syncthreads();
    }
    float inv = 1.f / (sqrtf(red[0]) + 1e-6f);
    for (int c = threadIdx.x; c < CF; c += blockDim.x) {
        float x = src[c] * inv;
        __nv_bfloat16 h = __float2bfloat16(x);
        dh[c] = h;
        dl[c] = __float2bfloat16(x - __bfloat162float(h));
    }
}

// =====================================================================
// gemm_nt_mma: C[1024,1024] = Ahi*Bhi^T + Alo*Bhi^T + Ahi*Blo^T
// single K pass: per 32-wide chunk load all 4 planes, 96 MMA/warp between syncs
// CTA 128x128, 8 warps (64x32 warp tile), PIPE=4, prefetch dist 2, 1 sync/chunk
// =====================================================================
#define KCH    32
#define NCH    (CF / KCH)        // 62
#define RSTR   80                // smem row stride bytes (conflict-free ldmatrix)
#define TILE_BYTES (128 * RSTR)  // 10240
#define STG_BYTES  (4 * TILE_BYTES)  // 40960: Ahi, Alo, Bhi, Blo
#define PIPE4  4
#define GEMM_SMEM (PIPE4 * STG_BYTES)  // 163840

__global__ __launch_bounds__(256) void gemm_nt_mma(
    const __nv_bfloat16* __restrict__ Ahi, const __nv_bfloat16* __restrict__ Alo,
    const __nv_bfloat16* __restrict__ Bhi, const __nv_bfloat16* __restrict__ Blo,
    float* __restrict__ Cg)
{
    extern __shared__ __align__(128) char smem[];
    uint32_t sbase = smem_u32(smem);
    int tid = threadIdx.x;
    int wid = tid >> 5, lane = tid & 31;
    int warp_m = wid & 1;          // 64-row half
    int warp_n = wid >> 1;         // 32-col quarter

    int b = blockIdx.z;
    int row0 = blockIdx.y * 128;
    int col0 = blockIdx.x * 128;

    const __nv_bfloat16* srcs[4] = {
        Ahi + ((size_t)b * NN + row0) * CF,
        Alo + ((size_t)b * NN + row0) * CF,
        Bhi + ((size_t)b * NN + col0) * CF,
        Blo + ((size_t)b * NN + col0) * CF };
    float* C = Cg + (size_t)b * NN * NN;

    float acc[4][4][4];
#pragma unroll
    for (int i = 0; i < 4; i++)
#pragma unroll
        for (int j = 0; j < 4; j++)
#pragma unroll
            for (int k = 0; k < 4; k++) acc[i][j][k] = 0.f;

    auto prefetch = [&](int c) {
        int kk = c * KCH;
        uint32_t stg = sbase + (c % PIPE4) * STG_BYTES;
#pragma unroll
        for (int it = 0; it < 8; it++) {
            int idx = it * 256 + tid;          // 0..2047
            int t = idx >> 9;                  // tile 0..3
            int w = idx & 511;
            int r = w >> 2, seg = w & 3;       // row 0..127, 16B seg 0..3
            cp_async16(stg + (uint32_t)(t * TILE_BYTES + r * RSTR + seg * 16),
                       srcs[t] + (size_t)r * CF + kk + seg * 8);
        }
    };

    prefetch(0); CP_COMMIT();
    prefetch(1); CP_COMMIT();

    // ldmatrix lane addressing (validated in R5)
    int a_row = (lane & 7) + ((lane >> 3) & 1) * 8;
    int a_k8  = (lane >> 4) * 8;
    int bg    = lane >> 3;
    int b_nat = bg >> 1;
    int b_k8  = (bg & 1) * 8;

    for (int c = 0; c < NCH; c++) {
        if (c + 2 < NCH) prefetch(c + 2);
        CP_COMMIT();
        CP_WAIT(2);
        __syncthreads();

        uint32_t stg = sbase + (c % PIPE4) * STG_BYTES;
        uint32_t sAh = stg, sAl = stg + TILE_BYTES;
        uint32_t sBh = stg + 2 * TILE_BYTES, sBl = stg + 3 * TILE_BYTES;
#pragma unroll
        for (int k16 = 0; k16 < 2; k16++) {
            int kb = k16 * 16;
            uint32_t afh[4][4], afl[4][4];
#pragma unroll
            for (int am = 0; am < 4; am++) {
                uint32_t off = (uint32_t)((warp_m * 64 + am * 16 + a_row) * RSTR + (kb + a_k8) * 2);
                ldsm_x4(afh[am], sAh + off);
                ldsm_x4(afl[am], sAl + off);
            }
            uint32_t bfh[4][2], bfl[4][2];
#pragma unroll
            for (int bp = 0; bp < 2; bp++) {
                uint32_t boff = (uint32_t)((warp_n * 32 + (bp * 2 + b_nat) * 8 + (lane & 7)) * RSTR
                                           + (kb + b_k8) * 2);
                uint32_t r4[4];
                ldsm_x4(r4, sBh + boff);
                bfh[bp * 2 + 0][0] = r4[0]; bfh[bp * 2 + 0][1] = r4[1];
                bfh[bp * 2 + 1][0] = r4[2]; bfh[bp * 2 + 1][1] = r4[3];
                ldsm_x4(r4, sBl + boff);
                bfl[bp * 2 + 0][0] = r4[0]; bfl[bp * 2 + 0][1] = r4[1];
                bfl[bp * 2 + 1][0] = r4[2]; bfl[bp * 2 + 1][1] = r4[3];
            }
#pragma unroll
            for (int am = 0; am < 4; am++)
#pragma unroll
                for (int an = 0; an < 4; an++) {
                    mma16816(acc[am][an], afh[am], bfh[an]);
                    mma16816(acc[am][an], afl[am], bfh[an]);
                    mma16816(acc[am][an], afh[am], bfl[an]);
                }
        }
    }

    int tr = lane >> 2, tc = (lane & 3) * 2;
#pragma unroll
    for (int am = 0; am < 4; am++)
#pragma unroll
        for (int an = 0; an < 4; an++) {
            int r = row0 + warp_m * 64 + am * 16 + tr;
            int cc = col0 + warp_n * 32 + an * 8 + tc;
            *(float2*)(C + (size_t)r * NN + cc) = make_float2(acc[am][an][0], acc[am][an][1]);
            *(float2*)(C + (size_t)(r + 8) * NN + cc) = make_float2(acc[am][an][2], acc[am][an][3]);
        }
}

// ---------------- row softmax over NN=1024, output split-bf16 ----------------
__global__ void softmax_split_rows(const float* __restrict__ Cmat,
                                   __nv_bfloat16* __restrict__ Ahi,
                                   __nv_bfloat16* __restrict__ Alo) {
    int row = blockIdx.x;
    const float* src = Cmat + (size_t)row * NN;
    __nv_bfloat16* dh = Ahi + (size_t)row * NN;
    __nv_bfloat16* dl = Alo + (size_t)row * NN;
    int tid = threadIdx.x;                  // 256
    float v[4];
    float m = -1e30f;
#pragma unroll
    for (int i = 0; i < 4; i++) { v[i] = src[tid + i * 256]; m = fmaxf(m, v[i]); }
    __shared__ float red[256];
    red[tid] = m; __syncthreads();
    for (int s = 128; s > 0; s >>= 1) { if (tid < s) red[tid] = fmaxf(red[tid], red[tid + s]); __syncthreads(); }
    m = red[0]; __syncthreads();
    float ssum = 0.f;
#pragma unroll
    for (int i = 0; i < 4; i++) { v[i] = __expf(v[i] - m); ssum += v[i]; }
    red[tid] = ssum; __syncthreads();
    for (int s = 128; s > 0; s >>= 1) { if (tid < s) red[tid] += red[tid + s]; __syncthreads(); }
    float inv = 1.f / red[0];
#pragma unroll
    for (int i = 0; i < 4; i++) {
        float x = v[i] * inv;
        __nv_bfloat16 h = __float2bfloat16(x);
        dh[tid + i * 256] = h;
        dl[tid + i * 256] = __float2bfloat16(x - __bfloat162float(h));
    }
}

// =====================================================================
// gemm_nn_mma: f_a[1024,128] = A[1024,1024] @ frabT[128,1024]^T (split-bf16)
// CTA 64x128, 4 warps (32x64 warp tile), KCH=32, PIPE=4 dist-2, 1 sync/chunk
// =====================================================================
#define NKCH   (NN / KCH)            // 32
#define AT_BYTES (64 * RSTR)         // 5120
#define BT_BYTES (128 * RSTR)        // 10240
#define STG2_BYTES (2 * AT_BYTES + 2 * BT_BYTES)  // 30720
#define GEMM2_SMEM (PIPE4 * STG2_BYTES)           // 122880

__global__ __launch_bounds__(128) void gemm_nn_mma(
    const __nv_bfloat16* __restrict__ Ahi, const __nv_bfloat16* __restrict__ Alo,
    const __nv_bfloat16* __restrict__ Bhi, const __nv_bfloat16* __restrict__ Blo,
    float* __restrict__ Fg)
{
    extern __shared__ __align__(128) char smem[];
    uint32_t sbase = smem_u32(smem);
    int tid = threadIdx.x;
    int wid = tid >> 5, lane = tid & 31;
    int warp_m = wid & 1;          // 32-row half
    int warp_n = wid >> 1;         // 64-col half

    int b = blockIdx.y;
    int mrow0 = blockIdx.x * 64;

    const __nv_bfloat16* Ah = Ahi + ((size_t)b * NN + mrow0) * NN;
    const __nv_bfloat16* Al = Alo + ((size_t)b * NN + mrow0) * NN;
    const __nv_bfloat16* Bh = Bhi + (size_t)b * 128 * NN;
    const __nv_bfloat16* Bl = Blo + (size_t)b * 128 * NN;
    float* F = Fg + (size_t)b * NN * 128;

    float acc[2][8][4];
#pragma unroll
    for (int i = 0; i < 2; i++)
#pragma unroll
        for (int j = 0; j < 8; j++)
#pragma unroll
            for (int k = 0; k < 4; k++) acc[i][j][k] = 0.f;

    auto prefetch = [&](int c) {
        int kk = c * KCH;
        uint32_t stg = sbase + (c % PIPE4) * STG2_BYTES;
#pragma unroll
        for (int it = 0; it < 12; it++) {
            int idx = it * 128 + tid;          // 0..1535
            if (idx < 512) {                   // A planes: 2 x 64 rows x 4 segs
                int pl = idx >> 8, w = idx & 255;
                int r = w >> 2, seg = w & 3;
                const __nv_bfloat16* s = pl ? Al : Ah;
                cp_async16(stg + (uint32_t)(pl * AT_BYTES + r * RSTR + seg * 16),
                           s + (size_t)r * NN + kk + seg * 8);
            } else {                           // B planes: 2 x 128 rows x 4 segs
                int w = idx - 512;
                int pl = w >> 9; w &= 511;
                int r = w >> 2, seg = w & 3;
                const __nv_bfloat16* s = pl ? Bl : Bh;
                cp_async16(stg + (uint32_t)(2 * AT_BYTES + pl * BT_BYTES + r * RSTR + seg * 16),
                           s + (size_t)r * NN + kk + seg * 8);
            }
        }
    };

    prefetch(0); CP_COMMIT();
    prefetch(1); CP_COMMIT();

    int a_row = (lane & 7) + ((lane >> 3) & 1) * 8;
    int a_k8  = (lane >> 4) * 8;
    int bg    = lane >> 3;
    int b_nat = bg >> 1;
    int b_k8  = (bg & 1) * 8;

    for (int c = 0; c < NKCH; c++) {
        if (c + 2 < NKCH) prefetch(c + 2);
        CP_COMMIT();
        CP_WAIT(2);
        __syncthreads();

        uint32_t stg = sbase + (c % PIPE4) * STG2_BYTES;
        uint32_t sAh = stg, sAl = stg + AT_BYTES;
        uint32_t sBh = stg + 2 * AT_BYTES, sBl = sBh + BT_BYTES;
#pragma unroll
        for (int k16 = 0; k16 < 2; k16++) {
            int kb = k16 * 16;
            uint32_t afh[2][4], afl[2][4];
#pragma unroll
            for (int am = 0; am < 2; am++) {
                uint32_t off = (uint32_t)((warp_m * 32 + am * 16 + a_row) * RSTR + (kb + a_k8) * 2);
                ldsm_x4(afh[am], sAh + off);
                ldsm_x4(afl[am], sAl + off);
            }
            uint32_t bfh[8][2], bfl[8][2];
#pragma unroll
            for (int bp = 0; bp < 4; bp++) {
                uint32_t boff = (uint32_t)((warp_n * 64 + (bp * 2 + b_nat) * 8 + (lane & 7)) * RSTR
                                           + (kb + b_k8) * 2);
                uint32_t r4[4];
                ldsm_x4(r4, sBh + boff);
                bfh[bp * 2 + 0][0] = r4[0]; bfh[bp * 2 + 0][1] = r4[1];
                bfh[bp * 2 + 1][0] = r4[2]; bfh[bp * 2 + 1][1] = r4[3];
                ldsm_x4(r4, sBl + boff);
                bfl[bp * 2 + 0][0] = r4[0]; bfl[bp * 2 + 0][1] = r4[1];
                bfl[bp * 2 + 1][0] = r4[2]; bfl[bp * 2 + 1][1] = r4[3];
            }
#pragma unroll
            for (int am = 0; am < 2; am++)
#pragma unroll
                for (int an = 0; an < 8; an++) {
                    mma16816(acc[am][an], afh[am], bfh[an]);
                    mma16816(acc[am][an], afl[am], bfh[an]);
                    mma16816(acc[am][an], afh[am], bfl[an]);
                }
        }
    }

    int tr = lane >> 2, tc = (lane & 3) * 2;
#pragma unroll
    for (int am = 0; am < 2; am++)
#pragma unroll
        for (int an = 0; an < 8; an++) {
            int r = mrow0 + warp_m * 32 + am * 16 + tr;
            int cc = warp_n * 64 + an * 8 + tc;
            *(float2*)(F + (size_t)r * 128 + cc) = make_float2(acc[am][an][0], acc[am][an][1]);
            *(float2*)(F + (size_t)(r + 8) * 128 + cc) = make_float2(acc[am][an][2], acc[am][an][3]);
        }
}

// ---------------- direct 3x3 conv + bias + relu, NHWC, blockDim.x == Cout ----------------
template <int TILE, int STRIDE>
__global__ void conv2d_relu_k(
    const float* __restrict__ in, const float* __restrict__ w,
    const float* __restrict__ bias, float* __restrict__ out,
    int Hin, int Win, int Cin, int Hout, int Wout, int Cout, int pad)
{
    constexpr int SPANX = (TILE - 1) * STRIDE + 3;
    extern __shared__ float sm[];           // [3][SPANX][Cin]
    int b = blockIdx.z;
    int oy = blockIdx.y;
    int ox0 = blockIdx.x * TILE;
    int co = threadIdx.x;

    int iy0 = oy * STRIDE - pad;
    int ix0 = ox0 * STRIDE - pad;
    int tot = 3 * SPANX * Cin;
    for (int i = threadIdx.x; i < tot; i += blockDim.x) {
        int ci = i % Cin; int rest = i / Cin;
        int xx = rest % SPANX; int r = rest / SPANX;
        int iy = iy0 + r, ix = ix0 + xx;
        float v = 0.f;
        if (iy >= 0 && iy < Hin && ix >= 0 && ix < Win)
            v = in[(((size_t)b * Hin + iy) * Win + ix) * Cin + ci];
        sm[(r * SPANX + xx) * Cin + ci] = v;
    }
    __syncthreads();

    float acc[TILE];
    float bv = bias[co];
#pragma unroll
    for (int p = 0; p < TILE; p++) acc[p] = bv;

    for (int r = 0; r < 3; r++)
        for (int kx = 0; kx < 3; kx++)
            for (int ci = 0; ci < Cin; ci++) {
                float wv = w[(size_t)((r * 3 + kx) * Cin + ci) * Cout + co];
                const float* srow = &sm[(r * SPANX + kx) * Cin + ci];
#pragma unroll
                for (int p = 0; p < TILE; p++)
                    acc[p] += srow[(size_t)p * STRIDE * Cin] * wv;
            }
#pragma unroll
    for (int p = 0; p < TILE; p++) {
        int ox = ox0 + p;
        out[(((size_t)b * Hout + oy) * Wout + ox) * Cout + co] = fmaxf(acc[p], 0.f);
    }
}

// ---- conv2 variant: stride-2 3x3, Cin=64, Cout=128, output TRANSPOSED bf16 hi/lo ----
__global__ void conv2_t_bf16(
    const float* __restrict__ in, const float* __restrict__ w,
    const float* __restrict__ bias,
    __nv_bfloat16* __restrict__ out_hi, __nv_bfloat16* __restrict__ out_lo)
{
    constexpr int TILE = 16, STRIDE = 2, SPANX = 33, CIN = 64, COUT = 128;
    extern __shared__ float sm[];           // [3][33][64]
    int b = blockIdx.z;
    int oy = blockIdx.y;                    // 0..31
    int ox0 = blockIdx.x * TILE;            // 0 or 16
    int co = threadIdx.x;                   // 128

    int iy0 = oy * STRIDE;
    int ix0 = ox0 * STRIDE;
    int tot = 3 * SPANX * CIN;
    for (int i = threadIdx.x; i < tot; i += COUT) {
        int ci = i % CIN; int rest = i / CIN;
        int xx = rest % SPANX; int r = rest / SPANX;
        int iy = iy0 + r, ix = ix0 + xx;
        float v = 0.f;
        if (iy < 64 && ix < 64)
            v = in[(((size_t)b * 64 + iy) * 64 + ix) * CIN + ci];
        sm[(r * SPANX + xx) * CIN + ci] = v;
    }
    __syncthreads();

    float acc[TILE];
    float bv = bias[co];
#pragma unroll
    for (int p = 0; p < TILE; p++) acc[p] = bv;

    for (int r = 0; r < 3; r++)
        for (int kx = 0; kx < 3; kx++)
            for (int ci = 0; ci < CIN; ci++) {
                float wv = w[(size_t)((r * 3 + kx) * CIN + ci) * COUT + co];
                const float* srow = &sm[(r * SPANX + kx) * CIN + ci];
#pragma unroll
                for (int p = 0; p < TILE; p++)
                    acc[p] += srow[(size_t)p * STRIDE * CIN] * wv;
            }
    __nv_bfloat16* dh = out_hi + ((size_t)b * COUT + co) * NN + oy * 32 + ox0;
    __nv_bfloat16* dl = out_lo + ((size_t)b * COUT + co) * NN + oy * 32 + ox0;
#pragma unroll
    for (int p = 0; p < TILE; p++) {
        float v = fmaxf(acc[p], 0.f);
        __nv_bfloat16 h = __float2bfloat16(v);
        dh[p] = h;
        dl[p] = __float2bfloat16(v - __bfloat162float(h));
    }
}

// ---------------- global max-pool over N positions ----------------
__global__ void maxpool_k(const float* __restrict__ t, float* __restrict__ mp) {
    int b = blockIdx.y;
    int c = blockIdx.x * blockDim.x + threadIdx.x;
    if (c >= CF) return;
    const float* src = t + (size_t)b * NN * CF + c;
    float m = -1e30f;
    for (int n = 0; n < NN; n++) m = fmaxf(m, src[(size_t)n * CF]);
    mp[b * CF + c] = m;
}

// ---------------- dense1: relu(mp @ w_d1 + b_d1) ----------------
__global__ void dense1_k(const float* __restrict__ mp, const float* __restrict__ w,
                         const float* __restrict__ bias, float* __restrict__ g1) {
    int b = blockIdx.x; int j = threadIdx.x;     // 512
    __shared__ float sm[CF];
    for (int k = threadIdx.x; k < CF; k += blockDim.x) sm[k] = mp[b * CF + k];
    __syncthreads();
    float s = bias[j];
    for (int k = 0; k < CF; k++) s += sm[k] * w[(size_t)k * 512 + j];
    g1[b * 512 + j] = fmaxf(s, 0.f);
}

// ---------------- dense2 + softmax ----------------
__global__ void dense2_softmax_k(const float* __restrict__ g1, const float* __restrict__ w,
                                 const float* __restrict__ bias, float* __restrict__ out) {
    int b = blockIdx.x;
    __shared__ float sg[512];
    __shared__ float logits[NCLS];
    __shared__ float red[256];
    int tid = threadIdx.x;                       // 256
    for (int k = tid; k < 512; k += 256) sg[k] = g1[b * 512 + k];
    __syncthreads();
    for (int j = tid; j < NCLS; j += 256) {
        float s = bias[j];
        for (int k = 0; k < 512; k++) s += sg[k] * w[(size_t)k * NCLS + j];
        logits[j] = s;
    }
    __syncthreads();
    float m = -1e30f;
    for (int j = tid; j < NCLS; j += 256) m = fmaxf(m, logits[j]);
    red[tid] = m; __syncthreads();
    for (int s = 128; s > 0; s >>= 1) { if (tid < s) red[tid] = fmaxf(red[tid], red[tid + s]); __syncthreads(); }
    m = red[0]; __syncthreads();
    float ssum = 0.f;
    for (int j = tid; j < NCLS; j += 256) { float e = __expf(logits[j] - m); logits[j] = e; ssum += e; }
    red[tid] = ssum; __syncthreads();
    for (int s = 128; s > 0; s >>= 1) { if (tid < s) red[tid] += red[tid + s]; __syncthreads(); }
    float inv = 1.f / red[0];
    for (int j = tid; j < NCLS; j += 256) out[b * NCLS + j] = logits[j] * inv;
}

// ---------------- launcher ----------------
extern "C" void kernel_launch(void* const* d_in, const int* in_sizes, int n_in,
                              void* d_out, int out_size) {
    const float* t_lum  = (const float*)d_in[0];
    const float* r_lum  = (const float*)d_in[1];
    const float* r_ab   = (const float*)d_in[2];
    const float* w_rab1 = (const float*)d_in[3];
    const float* b_rab1 = (const float*)d_in[4];
    const float* w_rab2 = (const float*)d_in[5];
    const float* b_rab2 = (const float*)d_in[6];
    const float* w_fa1  = (const float*)d_in[7];
    const float* b_fa1  = (const float*)d_in[8];
    const float* w_fa2  = (const float*)d_in[9];
    const float* b_fa2  = (const float*)d_in[10];
    const float* w_fa3  = (const float*)d_in[11];
    const float* b_fa3  = (const float*)d_in[12];
    const float* w_d1   = (const float*)d_in[13];
    const float* b_d1   = (const float*)d_in[14];
    const float* w_d2   = (const float*)d_in[15];
    const float* b_d2   = (const float*)d_in[16];

    __nv_bfloat16 *tnh, *tnl, *rnh, *rnl, *Ahi, *Alo, *fTh, *fTl;
    float *frab1, *fa, *mp, *g1;
    cudaGetSymbolAddress((void**)&tnh,   g_tn_hi);
    cudaGetSymbolAddress((void**)&tnl,   g_tn_lo);
    cudaGetSymbolAddress((void**)&rnh,   g_rn_hi);
    cudaGetSymbolAddress((void**)&rnl,   g_rn_lo);
    cudaGetSymbolAddress((void**)&Ahi,   g_A_hi);
    cudaGetSymbolAddress((void**)&Alo,   g_A_lo);
    cudaGetSymbolAddress((void**)&fTh,   g_frabT_hi);
    cudaGetSymbolAddress((void**)&fTl,   g_frabT_lo);
    cudaGetSymbolAddress((void**)&frab1, g_frab1);
    cudaGetSymbolAddress((void**)&fa,    g_fa);
    cudaGetSymbolAddress((void**)&mp,    g_mp);
    cudaGetSymbolAddress((void**)&g1,    g_g1);

    cudaFuncSetAttribute(gemm_nt_mma, cudaFuncAttributeMaxDynamicSharedMemorySize, GEMM_SMEM);
    cudaFuncSetAttribute(gemm_nn_mma, cudaFuncAttributeMaxDynamicSharedMemorySize, GEMM2_SMEM);

    float* out  = (float*)d_out;
    float* Cmat = out + 8000;          // [8,1024,1024]
    float* s1   = out + 8396608;       // [8,4,4,512]
    float* s2   = out + 8462144;       // [8,8,8,256]
    float* s3   = out + 8593216;       // [8,16,16,128]

    // 1,2: normalize + bf16 split
    normalize_split<<<NB * NN, 256>>>(t_lum, tnh, tnl);
    normalize_split<<<NB * NN, 256>>>(r_lum, rnh, rnl);

    // 3: chroma conv1 (independent -> moved up so gemm is the 4th launch for ncu)
    conv2d_relu_k<16, 1><<<dim3(64 / 16, 64, NB), 64, 3 * 18 * 2 * 4>>>(
        r_ab, w_rab1, b_rab1, frab1, 64, 64, 2, 64, 64, 64, 1);

    // 4: cost volume C = tn @ rn^T (split-bf16, mma.sync)  <- ncu capture slot
    gemm_nt_mma<<<dim3(8, 8, NB), 256, GEMM_SMEM>>>(tnh, tnl, rnh, rnl, Cmat);

    // 5: chroma conv2 -> transposed bf16 hi/lo
    conv2_t_bf16<<<dim3(2, 32, NB), 128, 3 * 33 * 64 * 4>>>(
        frab1, w_rab2, b_rab2, fTh, fTl);

    // 6: softmax -> split-bf16 A
    softmax_split_rows<<<NB * NN, 256>>>(Cmat, Ahi, Alo);

    // 7: attention f_a = A @ f_rab (split-bf16, mma.sync)
    gemm_nn_mma<<<dim3(NN / 64, NB), 128, GEMM2_SMEM>>>(Ahi, Alo, fTh, fTl, fa);

    // 8-10: pyramid
    conv2d_relu_k<8, 2><<<dim3(16 / 8, 16, NB), 128, 3 * 17 * 128 * 4>>>(
        fa, w_fa1, b_fa1, s3, 32, 32, 128, 16, 16, 128, 0);
    conv2d_relu_k<8, 2><<<dim3(8 / 8, 8, NB), 256, 3 * 17 * 128 * 4>>>(
        s3, w_fa2, b_fa2, s2, 16, 16, 128, 8, 8, 256, 0);
    conv2d_relu_k<4, 2><<<dim3(4 / 4, 4, NB), 512, 3 * 9 * 256 * 4>>>(
        s2, w_fa3, b_fa3, s1, 8, 8, 256, 4, 4, 512, 0);

    // 11-13: classifier head
    maxpool_k<<<dim3((CF + 255) / 256, NB), 256>>>(t_lum, mp);
    dense1_k<<<NB, 512>>>(mp, w_d1, b_d1, g1);
    dense2_softmax_k<<<NB, 256>>>(g1, w_d2, b_d2, out);
}

// round 7
// speedup vs baseline: 1.9933x; 1.4237x over previous
#include <cuda_runtime.h>
#include <cuda_fp16.h>
#include <math.h>
#include <stdint.h>

#define CF   1984
#define NB   8
#define NN   1024    // h*w = 32*32
#define NCLS 1000

// ---------------- scratch (static device globals; no allocation) ----------------
__device__ __half g_tn_hi[NB * NN * CF];
__device__ __half g_tn_lo[NB * NN * CF];
__device__ __half g_rn_hi[NB * NN * CF];
__device__ __half g_A_hi[NB * NN * NN];      // softmax(C) hi
__device__ __half g_A_lo[NB * NN * NN];      // softmax(C) lo
__device__ __half g_frabT_hi[NB * 128 * NN]; // f_rab transposed [b][ch][pos]
__device__ float g_frab1[NB * 64 * 64 * 64];
__device__ float g_fa[NB * NN * 128];
__device__ float g_mp[NB * CF];
__device__ float g_g1[NB * 512];

// ============================ helpers ============================
__device__ __forceinline__ uint32_t smem_u32(const void* p) {
    uint32_t a;
    asm("{ .reg .u64 t; cvta.to.shared.u64 t, %1; cvt.u32.u64 %0, t; }" : "=r"(a) : "l"(p));
    return a;
}
__device__ __forceinline__ void cp_async16(uint32_t dst, const void* src) {
    asm volatile("cp.async.cg.shared.global [%0], [%1], 16;" :: "r"(dst), "l"(src));
}
#define CP_COMMIT() asm volatile("cp.async.commit_group;" ::: "memory")
#define CP_WAIT(n)  asm volatile("cp.async.wait_group %0;" :: "n"(n) : "memory")

__device__ __forceinline__ void ldsm_x4(uint32_t* r, uint32_t addr) {
    asm volatile("ldmatrix.sync.aligned.m8n8.x4.shared.b16 {%0,%1,%2,%3}, [%4];"
                 : "=r"(r[0]), "=r"(r[1]), "=r"(r[2]), "=r"(r[3]) : "r"(addr));
}
__device__ __forceinline__ void mma16816(float* d, const uint32_t* a, const uint32_t* b) {
    asm volatile(
        "mma.sync.aligned.m16n8k16.row.col.f32.f16.f16.f32 "
        "{%0,%1,%2,%3}, {%4,%5,%6,%7}, {%8,%9}, {%0,%1,%2,%3};"
        : "+f"(d[0]), "+f"(d[1]), "+f"(d[2]), "+f"(d[3])
        : "r"(a[0]), "r"(a[1]), "r"(a[2]), "r"(a[3]), "r"(b[0]), "r"(b[1]));
}

// ---------------- normalize + fp16 hi/lo split (hi+lo for t) ----------------
__global__ void normalize_split_hl(const float* __restrict__ in,
                                   __half* __restrict__ hi, __half* __restrict__ lo) {
    int row = blockIdx.x;
    const float* src = in + (size_t)row * CF;
    __half* dh = hi + (size_t)row * CF;
    __half* dl = lo + (size_t)row * CF;
    float ss = 0.f;
#pragma unroll 8
    for (int c = threadIdx.x; c < CF; c += 256) { float v = src[c]; ss += v * v; }
    __shared__ float red[256];
    red[threadIdx.x] = ss; __syncthreads();
    for (int s = 128; s > 0; s >>= 1) {
        if (threadIdx.x < s) red[threadIdx.x] += red[threadIdx.x + s];
        __syncthreads();
    }
    float inv = 1.f / (sqrtf(red[0]) + 1e-6f);
#pragma unroll 8
    for (int c = threadIdx.x; c < CF; c += 256) {
        float x = src[c] * inv;
        __half h = __float2half_rn(x);
        dh[c] = h;
        dl[c] = __float2half_rn(x - __half2float(h));
    }
}
// hi-only for r
__global__ void normalize_split_h(const float* __restrict__ in, __half* __restrict__ hi) {
    int row = blockIdx.x;
    const float* src = in + (size_t)row * CF;
    __half* dh = hi + (size_t)row * CF;
    float ss = 0.f;
#pragma unroll 8
    for (int c = threadIdx.x; c < CF; c += 256) { float v = src[c]; ss += v * v; }
    __shared__ float red[256];
    red[threadIdx.x] = ss; __syncthreads();
    for (int s = 128; s > 0; s >>= 1) {
        if (threadIdx.x < s) red[threadIdx.x] += red[threadIdx.x + s];
        __syncthreads();
    }
    float inv = 1.f / (sqrtf(red[0]) + 1e-6f);
#pragma unroll 8
    for (int c = threadIdx.x; c < CF; c += 256) dh[c] = __float2half_rn(src[c] * inv);
}

// =====================================================================
// gemm_nt_mma: C = Ah*Bh^T + Al*Bh^T   (2-term fp16 split)
// CTA 128x128, 8 warps 64x32 tile, KCH=32, 3 tiles/chunk, PIPE=4 dist-2
// =====================================================================
#define KCH    32
#define NCH    (CF / KCH)        // 62
#define RSTR   80
#define TILE_BYTES (128 * RSTR)          // 10240
#define STG_BYTES  (3 * TILE_BYTES)      // 30720: Ah, Al, Bh
#define PIPE4  4
#define GEMM_SMEM (PIPE4 * STG_BYTES)    // 122880

__global__ __launch_bounds__(256) void gemm_nt_mma(
    const __half* __restrict__ Ahi, const __half* __restrict__ Alo,
    const __half* __restrict__ Bhi, float* __restrict__ Cg)
{
    extern __shared__ __align__(128) char smem[];
    uint32_t sbase = smem_u32(smem);
    int tid = threadIdx.x;
    int wid = tid >> 5, lane = tid & 31;
    int warp_m = wid & 1;
    int warp_n = wid >> 1;

    int b = blockIdx.z;
    int row0 = blockIdx.y * 128;
    int col0 = blockIdx.x * 128;

    const __half* srcs[3] = {
        Ahi + ((size_t)b * NN + row0) * CF,
        Alo + ((size_t)b * NN + row0) * CF,
        Bhi + ((size_t)b * NN + col0) * CF };
    float* C = Cg + (size_t)b * NN * NN;

    float acc[4][4][4];
#pragma unroll
    for (int i = 0; i < 4; i++)
#pragma unroll
        for (int j = 0; j < 4; j++)
#pragma unroll
            for (int k = 0; k < 4; k++) acc[i][j][k] = 0.f;

    auto prefetch = [&](int c) {
        int kk = c * KCH;
        uint32_t stg = sbase + (c % PIPE4) * STG_BYTES;
#pragma unroll
        for (int it = 0; it < 6; it++) {
            int idx = it * 256 + tid;          // 0..1535
            int t = idx >> 9;                  // tile 0..2
            int w = idx & 511;
            int r = w >> 2, seg = w & 3;
            cp_async16(stg + (uint32_t)(t * TILE_BYTES + r * RSTR + seg * 16),
                       srcs[t] + (size_t)r * CF + kk + seg * 8);
        }
    };

    prefetch(0); CP_COMMIT();
    prefetch(1); CP_COMMIT();

    int a_row = (lane & 7) + ((lane >> 3) & 1) * 8;
    int a_k8  = (lane >> 4) * 8;
    int bg    = lane >> 3;
    int b_nat = bg >> 1;
    int b_k8  = (bg & 1) * 8;

    for (int c = 0; c < NCH; c++) {
        if (c + 2 < NCH) prefetch(c + 2);
        CP_COMMIT();
        CP_WAIT(2);
        __syncthreads();

        uint32_t stg = sbase + (c % PIPE4) * STG_BYTES;
        uint32_t sAh = stg, sAl = stg + TILE_BYTES, sBh = stg + 2 * TILE_BYTES;
#pragma unroll
        for (int k16 = 0; k16 < 2; k16++) {
            int kb = k16 * 16;
            uint32_t afh[4][4], afl[4][4];
#pragma unroll
            for (int am = 0; am < 4; am++) {
                uint32_t off = (uint32_t)((warp_m * 64 + am * 16 + a_row) * RSTR + (kb + a_k8) * 2);
                ldsm_x4(afh[am], sAh + off);
                ldsm_x4(afl[am], sAl + off);
            }
            uint32_t bfh[4][2];
#pragma unroll
            for (int bp = 0; bp < 2; bp++) {
                uint32_t boff = (uint32_t)((warp_n * 32 + (bp * 2 + b_nat) * 8 + (lane & 7)) * RSTR
                                           + (kb + b_k8) * 2);
                uint32_t r4[4];
                ldsm_x4(r4, sBh + boff);
                bfh[bp * 2 + 0][0] = r4[0]; bfh[bp * 2 + 0][1] = r4[1];
                bfh[bp * 2 + 1][0] = r4[2]; bfh[bp * 2 + 1][1] = r4[3];
            }
#pragma unroll
            for (int am = 0; am < 4; am++)
#pragma unroll
                for (int an = 0; an < 4; an++) {
                    mma16816(acc[am][an], afh[am], bfh[an]);
                    mma16816(acc[am][an], afl[am], bfh[an]);
                }
        }
    }

    int tr = lane >> 2, tc = (lane & 3) * 2;
#pragma unroll
    for (int am = 0; am < 4; am++)
#pragma unroll
        for (int an = 0; an < 4; an++) {
            int r = row0 + warp_m * 64 + am * 16 + tr;
            int cc = col0 + warp_n * 32 + an * 8 + tc;
            *(float2*)(C + (size_t)r * NN + cc) = make_float2(acc[am][an][0], acc[am][an][1]);
            *(float2*)(C + (size_t)(r + 8) * NN + cc) = make_float2(acc[am][an][2], acc[am][an][3]);
        }
}

// ---------------- row softmax over NN=1024, output split-fp16 ----------------
__global__ void softmax_split_rows(const float* __restrict__ Cmat,
                                   __half* __restrict__ Ahi, __half* __restrict__ Alo) {
    int row = blockIdx.x;
    const float* src = Cmat + (size_t)row * NN;
    __half* dh = Ahi + (size_t)row * NN;
    __half* dl = Alo + (size_t)row * NN;
    int tid = threadIdx.x;                  // 256
    float v[4];
    float m = -1e30f;
#pragma unroll
    for (int i = 0; i < 4; i++) { v[i] = src[tid + i * 256]; m = fmaxf(m, v[i]); }
    __shared__ float red[256];
    red[tid] = m; __syncthreads();
    for (int s = 128; s > 0; s >>= 1) { if (tid < s) red[tid] = fmaxf(red[tid], red[tid + s]); __syncthreads(); }
    m = red[0]; __syncthreads();
    float ssum = 0.f;
#pragma unroll
    for (int i = 0; i < 4; i++) { v[i] = __expf(v[i] - m); ssum += v[i]; }
    red[tid] = ssum; __syncthreads();
    for (int s = 128; s > 0; s >>= 1) { if (tid < s) red[tid] += red[tid + s]; __syncthreads(); }
    float inv = 1.f / red[0];
#pragma unroll
    for (int i = 0; i < 4; i++) {
        float x = v[i] * inv;
        __half h = __float2half_rn(x);
        dh[tid + i * 256] = h;
        dl[tid + i * 256] = __float2half_rn(x - __half2float(h));
    }
}

// =====================================================================
// gemm_nn_mma: f_a[1024,128] = (Ah+Al) @ Bh^T   (2-term fp16)
// CTA 64x128, 8 warps (32x32 warp tile), KCH=32, PIPE=4 dist-2
// =====================================================================
#define NKCH   (NN / KCH)            // 32
#define AT_BYTES (64 * RSTR)         // 5120
#define BT_BYTES (128 * RSTR)        // 10240
#define STG2_BYTES (2 * AT_BYTES + BT_BYTES)      // 20480
#define GEMM2_SMEM (PIPE4 * STG2_BYTES)           // 81920

__global__ __launch_bounds__(256) void gemm_nn_mma(
    const __half* __restrict__ Ahi, const __half* __restrict__ Alo,
    const __half* __restrict__ Bhi, float* __restrict__ Fg)
{
    extern __shared__ __align__(128) char smem[];
    uint32_t sbase = smem_u32(smem);
    int tid = threadIdx.x;
    int wid = tid >> 5, lane = tid & 31;
    int warp_m = wid & 1;          // 32-row half
    int warp_n = wid >> 1;         // 0..3, 32 cols each

    int b = blockIdx.y;
    int mrow0 = blockIdx.x * 64;

    const __half* Ah = Ahi + ((size_t)b * NN + mrow0) * NN;
    const __half* Al = Alo + ((size_t)b * NN + mrow0) * NN;
    const __half* Bh = Bhi + (size_t)b * 128 * NN;
    float* F = Fg + (size_t)b * NN * 128;

    float acc[2][4][4];
#pragma unroll
    for (int i = 0; i < 2; i++)
#pragma unroll
        for (int j = 0; j < 4; j++)
#pragma unroll
            for (int k = 0; k < 4; k++) acc[i][j][k] = 0.f;

    auto prefetch = [&](int c) {
        int kk = c * KCH;
        uint32_t stg = sbase + (c % PIPE4) * STG2_BYTES;
#pragma unroll
        for (int it = 0; it < 4; it++) {
            int idx = it * 256 + tid;          // 0..1023
            if (idx < 512) {                   // A hi/lo: 2 x 64 rows x 4 segs
                int pl = idx >> 8, w = idx & 255;
                int r = w >> 2, seg = w & 3;
                const __half* s = pl ? Al : Ah;
                cp_async16(stg + (uint32_t)(pl * AT_BYTES + r * RSTR + seg * 16),
                           s + (size_t)r * NN + kk + seg * 8);
            } else {                           // B hi: 128 rows x 4 segs
                int w = idx - 512;
                int r = w >> 2, seg = w & 3;
                cp_async16(stg + (uint32_t)(2 * AT_BYTES + r * RSTR + seg * 16),
                           Bh + (size_t)r * NN + kk + seg * 8);
            }
        }
    };

    prefetch(0); CP_COMMIT();
    prefetch(1); CP_COMMIT();

    int a_row = (lane & 7) + ((lane >> 3) & 1) * 8;
    int a_k8  = (lane >> 4) * 8;
    int bg    = lane >> 3;
    int b_nat = bg >> 1;
    int b_k8  = (bg & 1) * 8;

    for (int c = 0; c < NKCH; c++) {
        if (c + 2 < NKCH) prefetch(c + 2);
        CP_COMMIT();
        CP_WAIT(2);
        __syncthreads();

        uint32_t stg = sbase + (c % PIPE4) * STG2_BYTES;
        uint32_t sAh = stg, sAl = stg + AT_BYTES, sBh = stg + 2 * AT_BYTES;
#pragma unroll
        for (int k16 = 0; k16 < 2; k16++) {
            int kb = k16 * 16;
            uint32_t afh[2][4], afl[2][4];
#pragma unroll
            for (int am = 0; am < 2; am++) {
                uint32_t off = (uint32_t)((warp_m * 32 + am * 16 + a_row) * RSTR + (kb + a_k8) * 2);
                ldsm_x4(afh[am], sAh + off);
                ldsm_x4(afl[am], sAl + off);
            }
            uint32_t bfh[4][2];
#pragma unroll
            for (int bp = 0; bp < 2; bp++) {
                uint32_t boff = (uint32_t)((warp_n * 32 + (bp * 2 + b_nat) * 8 + (lane & 7)) * RSTR
                                           + (kb + b_k8) * 2);
                uint32_t r4[4];
                ldsm_x4(r4, sBh + boff);
                bfh[bp * 2 + 0][0] = r4[0]; bfh[bp * 2 + 0][1] = r4[1];
                bfh[bp * 2 + 1][0] = r4[2]; bfh[bp * 2 + 1][1] = r4[3];
            }
#pragma unroll
            for (int am = 0; am < 2; am++)
#pragma unroll
                for (int an = 0; an < 4; an++) {
                    mma16816(acc[am][an], afh[am], bfh[an]);
                    mma16816(acc[am][an], afl[am], bfh[an]);
                }
        }
    }

    int tr = lane >> 2, tc = (lane & 3) * 2;
#pragma unroll
    for (int am = 0; am < 2; am++)
#pragma unroll
        for (int an = 0; an < 4; an++) {
            int r = mrow0 + warp_m * 32 + am * 16 + tr;
            int cc = warp_n * 32 + an * 8 + tc;
            *(float2*)(F + (size_t)r * 128 + cc) = make_float2(acc[am][an][0], acc[am][an][1]);
            *(float2*)(F + (size_t)(r + 8) * 128 + cc) = make_float2(acc[am][an][2], acc[am][an][3]);
        }
}

// ------- templated direct 3x3 conv + bias + relu, NHWC, compile-time CIN -------
template <int TILE, int STRIDE, int CIN>
__global__ void conv2d_relu_t(
    const float* __restrict__ in, const float* __restrict__ w,
    const float* __restrict__ bias, float* __restrict__ out,
    int Hin, int Win, int Hout, int Wout, int Cout, int pad)
{
    constexpr int SPANX = (TILE - 1) * STRIDE + 3;
    extern __shared__ float sm[];           // [3][SPANX][CIN]
    int b = blockIdx.z;
    int oy = blockIdx.y;
    int ox0 = blockIdx.x * TILE;
    int co = threadIdx.x;

    int iy0 = oy * STRIDE - pad;
    int ix0 = ox0 * STRIDE - pad;
    constexpr int TOT = 3 * SPANX * CIN;
    for (int i = threadIdx.x; i < TOT; i += blockDim.x) {
        int ci = i % CIN; int rest = i / CIN;
        int xx = rest % SPANX; int r = rest / SPANX;
        int iy = iy0 + r, ix = ix0 + xx;
        float v = 0.f;
        if (iy >= 0 && iy < Hin && ix >= 0 && ix < Win)
            v = in[(((size_t)b * Hin + iy) * Win + ix) * CIN + ci];
        sm[(r * SPANX + xx) * CIN + ci] = v;
    }
    __syncthreads();

    float acc[TILE];
    float bv = bias[co];
#pragma unroll
    for (int p = 0; p < TILE; p++) acc[p] = bv;

#pragma unroll
    for (int r = 0; r < 3; r++)
#pragma unroll
        for (int kx = 0; kx < 3; kx++) {
#pragma unroll 8
            for (int ci = 0; ci < CIN; ci++) {
                float wv = w[(size_t)((r * 3 + kx) * CIN + ci) * Cout + co];
                const float* srow = &sm[(r * SPANX + kx) * CIN + ci];
#pragma unroll
                for (int p = 0; p < TILE; p++)
                    acc[p] += srow[(size_t)p * STRIDE * CIN] * wv;
            }
        }
#pragma unroll
    for (int p = 0; p < TILE; p++) {
        int ox = ox0 + p;
        out[(((size_t)b * Hout + oy) * Wout + ox) * Cout + co] = fmaxf(acc[p], 0.f);
    }
}

// ---- conv2: stride-2 3x3, Cin=64 -> Cout=128, TRANSPOSED fp16 hi output ----
__global__ void conv2_t_fp16(
    const float* __restrict__ in, const float* __restrict__ w,
    const float* __restrict__ bias, __half* __restrict__ out_hi)
{
    constexpr int TILE = 16, STRIDE = 2, SPANX = 33, CIN = 64, COUT = 128;
    extern __shared__ float sm[];           // [3][33][64]
    int b = blockIdx.z;
    int oy = blockIdx.y;
    int ox0 = blockIdx.x * TILE;
    int co = threadIdx.x;

    int iy0 = oy * STRIDE;
    int ix0 = ox0 * STRIDE;
    constexpr int TOT = 3 * SPANX * CIN;
    for (int i = threadIdx.x; i < TOT; i += COUT) {
        int ci = i % CIN; int rest = i / CIN;
        int xx = rest % SPANX; int r = rest / SPANX;
        int iy = iy0 + r, ix = ix0 + xx;
        float v = 0.f;
        if (iy < 64 && ix < 64)
            v = in[(((size_t)b * 64 + iy) * 64 + ix) * CIN + ci];
        sm[(r * SPANX + xx) * CIN + ci] = v;
    }
    __syncthreads();

    float acc[TILE];
    float bv = bias[co];
#pragma unroll
    for (int p = 0; p < TILE; p++) acc[p] = bv;

#pragma unroll
    for (int r = 0; r < 3; r++)
#pragma unroll
        for (int kx = 0; kx < 3; kx++) {
#pragma unroll 8
            for (int ci = 0; ci < CIN; ci++) {
                float wv = w[(size_t)((r * 3 + kx) * CIN + ci) * COUT + co];
                const float* srow = &sm[(r * SPANX + kx) * CIN + ci];
#pragma unroll
                for (int p = 0; p < TILE; p++)
                    acc[p] += srow[(size_t)p * STRIDE * CIN] * wv;
            }
        }
    __half* dh = out_hi + ((size_t)b * COUT + co) * NN + oy * 32 + ox0;
#pragma unroll
    for (int p = 0; p < TILE; p++)
        dh[p] = __float2half_rn(fmaxf(acc[p], 0.f));
}

// ---------------- global max-pool over N positions ----------------
__global__ void maxpool_k(const float* __restrict__ t, float* __restrict__ mp) {
    int b = blockIdx.y;
    int c = blockIdx.x * blockDim.x + threadIdx.x;
    if (c >= CF) return;
    const float* src = t + (size_t)b * NN * CF + c;
    float m = -1e30f;
#pragma unroll 8
    for (int n = 0; n < NN; n++) m = fmaxf(m, src[(size_t)n * CF]);
    mp[b * CF + c] = m;
}

// ---------------- dense1: relu(mp @ w_d1 + b_d1) ----------------
__global__ void dense1_k(const float* __restrict__ mp, const float* __restrict__ w,
                         const float* __restrict__ bias, float* __restrict__ g1) {
    int b = blockIdx.x; int j = threadIdx.x;     // 512
    __shared__ float sm[CF];
    for (int k = threadIdx.x; k < CF; k += blockDim.x) sm[k] = mp[b * CF + k];
    __syncthreads();
    float s = bias[j];
#pragma unroll 8
    for (int k = 0; k < CF; k++) s += sm[k] * w[(size_t)k * 512 + j];
    g1[b * 512 + j] = fmaxf(s, 0.f);
}

// ---------------- dense2 + softmax ----------------
__global__ void dense2_softmax_k(const float* __restrict__ g1, const float* __restrict__ w,
                                 const float* __restrict__ bias, float* __restrict__ out) {
    int b = blockIdx.x;
    __shared__ float sg[512];
    __shared__ float logits[NCLS];
    __shared__ float red[256];
    int tid = threadIdx.x;                       // 256
    for (int k = tid; k < 512; k += 256) sg[k] = g1[b * 512 + k];
    __syncthreads();
    for (int j = tid; j < NCLS; j += 256) {
        float s = bias[j];
#pragma unroll 8
        for (int k = 0; k < 512; k++) s += sg[k] * w[(size_t)k * NCLS + j];
        logits[j] = s;
    }
    __syncthreads();
    float m = -1e30f;
    for (int j = tid; j < NCLS; j += 256) m = fmaxf(m, logits[j]);
    red[tid] = m; __syncthreads();
    for (int s = 128; s > 0; s >>= 1) { if (tid < s) red[tid] = fmaxf(red[tid], red[tid + s]); __syncthreads(); }
    m = red[0]; __syncthreads();
    float ssum = 0.f;
    for (int j = tid; j < NCLS; j += 256) { float e = __expf(logits[j] - m); logits[j] = e; ssum += e; }
    red[tid] = ssum; __syncthreads();
    for (int s = 128; s > 0; s >>= 1) { if (tid < s) red[tid] += red[tid + s]; __syncthreads(); }
    float inv = 1.f / red[0];
    for (int j = tid; j < NCLS; j += 256) out[b * NCLS + j] = logits[j] * inv;
}

// ---------------- launcher ----------------
extern "C" void kernel_launch(void* const* d_in, const int* in_sizes, int n_in,
                              void* d_out, int out_size) {
    const float* t_lum  = (const float*)d_in[0];
    const float* r_lum  = (const float*)d_in[1];
    const float* r_ab   = (const float*)d_in[2];
    const float* w_rab1 = (const float*)d_in[3];
    const float* b_rab1 = (const float*)d_in[4];
    const float* w_rab2 = (const float*)d_in[5];
    const float* b_rab2 = (const float*)d_in[6];
    const float* w_fa1  = (const float*)d_in[7];
    const float* b_fa1  = (const float*)d_in[8];
    const float* w_fa2  = (const float*)d_in[9];
    const float* b_fa2  = (const float*)d_in[10];
    const float* w_fa3  = (const float*)d_in[11];
    const float* b_fa3  = (const float*)d_in[12];
    const float* w_d1   = (const float*)d_in[13];
    const float* b_d1   = (const float*)d_in[14];
    const float* w_d2   = (const float*)d_in[15];
    const float* b_d2   = (const float*)d_in[16];

    __half *tnh, *tnl, *rnh, *Ahi, *Alo, *fTh;
    float *frab1, *fa, *mp, *g1;
    cudaGetSymbolAddress((void**)&tnh,   g_tn_hi);
    cudaGetSymbolAddress((void**)&tnl,   g_tn_lo);
    cudaGetSymbolAddress((void**)&rnh,   g_rn_hi);
    cudaGetSymbolAddress((void**)&Ahi,   g_A_hi);
    cudaGetSymbolAddress((void**)&Alo,   g_A_lo);
    cudaGetSymbolAddress((void**)&fTh,   g_frabT_hi);
    cudaGetSymbolAddress((void**)&frab1, g_frab1);
    cudaGetSymbolAddress((void**)&fa,    g_fa);
    cudaGetSymbolAddress((void**)&mp,    g_mp);
    cudaGetSymbolAddress((void**)&g1,    g_g1);

    cudaFuncSetAttribute(gemm_nt_mma, cudaFuncAttributeMaxDynamicSharedMemorySize, GEMM_SMEM);
    cudaFuncSetAttribute(gemm_nn_mma, cudaFuncAttributeMaxDynamicSharedMemorySize, GEMM2_SMEM);

    float* out  = (float*)d_out;
    float* Cmat = out + 8000;          // [8,1024,1024]
    float* s1   = out + 8396608;       // [8,4,4,512]
    float* s2   = out + 8462144;       // [8,8,8,256]
    float* s3   = out + 8593216;       // [8,16,16,128]

    // 1,2: normalize + fp16 split
    normalize_split_hl<<<NB * NN, 256>>>(t_lum, tnh, tnl);
    normalize_split_h<<<NB * NN, 256>>>(r_lum, rnh);

    // 3: chroma conv1
    conv2d_relu_t<16, 1, 2><<<dim3(4, 64, NB), 64, 3 * 18 * 2 * 4>>>(
        r_ab, w_rab1, b_rab1, frab1, 64, 64, 64, 64, 64, 1);

    // 4: chroma conv2 -> transposed fp16   <- profile slot
    conv2_t_fp16<<<dim3(2, 32, NB), 128, 3 * 33 * 64 * 4>>>(
        frab1, w_rab2, b_rab2, fTh);

    // 5: cost volume C = tn @ rn^T (2-term fp16 split, mma.sync)
    gemm_nt_mma<<<dim3(8, 8, NB), 256, GEMM_SMEM>>>(tnh, tnl, rnh, Cmat);

    // 6: softmax -> split-fp16 A
    softmax_split_rows<<<NB * NN, 256>>>(Cmat, Ahi, Alo);

    // 7: attention f_a = A @ f_rab
    gemm_nn_mma<<<dim3(NN / 64, NB), 256, GEMM2_SMEM>>>(Ahi, Alo, fTh, fa);

    // 8-10: pyramid
    conv2d_relu_t<8, 2, 128><<<dim3(2, 16, NB), 128, 3 * 17 * 128 * 4>>>(
        fa, w_fa1, b_fa1, s3, 32, 32, 16, 16, 128, 0);
    conv2d_relu_t<8, 2, 128><<<dim3(1, 8, NB), 256, 3 * 17 * 128 * 4>>>(
        s3, w_fa2, b_fa2, s2, 16, 16, 8, 8, 256, 0);
    conv2d_relu_t<4, 2, 256><<<dim3(1, 4, NB), 512, 3 * 9 * 256 * 4>>>(
        s2, w_fa3, b_fa3, s1, 8, 8, 4, 4, 512, 0);

    // 11-13: classifier head
    maxpool_k<<<dim3((CF + 255) / 256, NB), 256>>>(t_lum, mp);
    dense1_k<<<NB, 512>>>(mp, w_d1, b_d1, g1);
    dense2_softmax_k<<<NB, 256>>>(g1, w_d2, b_d2, out);
}

// round 8
// speedup vs baseline: 3.1824x; 1.5965x over previous
#include <cuda_runtime.h>
#include <cuda_fp16.h>
#include <math.h>
#include <stdint.h>

#define CF   1984
#define NB   8
#define NN   1024    // h*w = 32*32
#define NCLS 1000

// ---------------- scratch (static device globals; no allocation) ----------------
__device__ __half g_tn_hi[NB * NN * CF];
__device__ __half g_tn_lo[NB * NN * CF];
__device__ __half g_rn_hi[NB * NN * CF];
__device__ __half g_A_hi[NB * NN * NN];
__device__ __half g_A_lo[NB * NN * NN];
__device__ __half g_frabT_hi[NB * 128 * NN];
__device__ float g_frab1[NB * 64 * 64 * 64];
__device__ float g_fa[NB * NN * 128];
__device__ float g_mpp[8 * NB * CF];     // maxpool partials [ns][b][c]
__device__ float g_mp[NB * CF];
__device__ float g_d1p[8 * NB * 512];    // dense1 partials [ks][b][j]
__device__ float g_g1[NB * 512];
__device__ float g_logits[NB * NCLS];

// ============================ helpers ============================
__device__ __forceinline__ uint32_t smem_u32(const void* p) {
    uint32_t a;
    asm("{ .reg .u64 t; cvta.to.shared.u64 t, %1; cvt.u32.u64 %0, t; }" : "=r"(a) : "l"(p));
    return a;
}
__device__ __forceinline__ void cp_async16(uint32_t dst, const void* src) {
    asm volatile("cp.async.cg.shared.global [%0], [%1], 16;" :: "r"(dst), "l"(src));
}
#define CP_COMMIT() asm volatile("cp.async.commit_group;" ::: "memory")
#define CP_WAIT(n)  asm volatile("cp.async.wait_group %0;" :: "n"(n) : "memory")

__device__ __forceinline__ void ldsm_x4(uint32_t* r, uint32_t addr) {
    asm volatile("ldmatrix.sync.aligned.m8n8.x4.shared.b16 {%0,%1,%2,%3}, [%4];"
                 : "=r"(r[0]), "=r"(r[1]), "=r"(r[2]), "=r"(r[3]) : "r"(addr));
}
__device__ __forceinline__ void mma16816(float* d, const uint32_t* a, const uint32_t* b) {
    asm volatile(
        "mma.sync.aligned.m16n8k16.row.col.f32.f16.f16.f32 "
        "{%0,%1,%2,%3}, {%4,%5,%6,%7}, {%8,%9}, {%0,%1,%2,%3};"
        : "+f"(d[0]), "+f"(d[1]), "+f"(d[2]), "+f"(d[3])
        : "r"(a[0]), "r"(a[1]), "r"(a[2]), "r"(a[3]), "r"(b[0]), "r"(b[1]));
}

// ---------------- normalize + fp16 hi/lo split (register-cached) ----------------
__global__ void normalize_split_hl(const float* __restrict__ in,
                                   __half* __restrict__ hi, __half* __restrict__ lo) {
    int row = blockIdx.x;
    const float* src = in + (size_t)row * CF;
    __half* dh = hi + (size_t)row * CF;
    __half* dl = lo + (size_t)row * CF;
    float v[8];
    float ss = 0.f;
#pragma unroll
    for (int i = 0; i < 8; i++) {
        int c = threadIdx.x + i * 256;
        v[i] = (c < CF) ? src[c] : 0.f;
        ss += v[i] * v[i];
    }
    __shared__ float red[256];
    red[threadIdx.x] = ss; __syncthreads();
    for (int s = 128; s > 0; s >>= 1) {
        if (threadIdx.x < s) red[threadIdx.x] += red[threadIdx.x + s];
        __syncthreads();
    }
    float inv = 1.f / (sqrtf(red[0]) + 1e-6f);
#pragma unroll
    for (int i = 0; i < 8; i++) {
        int c = threadIdx.x + i * 256;
        if (c < CF) {
            float x = v[i] * inv;
            __half h = __float2half_rn(x);
            dh[c] = h;
            dl[c] = __float2half_rn(x - __half2float(h));
        }
    }
}
__global__ void normalize_split_h(const float* __restrict__ in, __half* __restrict__ hi) {
    int row = blockIdx.x;
    const float* src = in + (size_t)row * CF;
    __half* dh = hi + (size_t)row * CF;
    float v[8];
    float ss = 0.f;
#pragma unroll
    for (int i = 0; i < 8; i++) {
        int c = threadIdx.x + i * 256;
        v[i] = (c < CF) ? src[c] : 0.f;
        ss += v[i] * v[i];
    }
    __shared__ float red[256];
    red[threadIdx.x] = ss; __syncthreads();
    for (int s = 128; s > 0; s >>= 1) {
        if (threadIdx.x < s) red[threadIdx.x] += red[threadIdx.x + s];
        __syncthreads();
    }
    float inv = 1.f / (sqrtf(red[0]) + 1e-6f);
#pragma unroll
    for (int i = 0; i < 8; i++) {
        int c = threadIdx.x + i * 256;
        if (c < CF) dh[c] = __float2half_rn(v[i] * inv);
    }
}

// =====================================================================
// gemm_nt_mma: C = Ah*Bh^T + Al*Bh^T   (2-term fp16 split)
// =====================================================================
#define KCH    32
#define NCH    (CF / KCH)        // 62
#define RSTR   80
#define TILE_BYTES (128 * RSTR)          // 10240
#define STG_BYTES  (3 * TILE_BYTES)      // 30720
#define PIPE4  4
#define GEMM_SMEM (PIPE4 * STG_BYTES)    // 122880

__global__ __launch_bounds__(256) void gemm_nt_mma(
    const __half* __restrict__ Ahi, const __half* __restrict__ Alo,
    const __half* __restrict__ Bhi, float* __restrict__ Cg)
{
    extern __shared__ __align__(128) char smem[];
    uint32_t sbase = smem_u32(smem);
    int tid = threadIdx.x;
    int wid = tid >> 5, lane = tid & 31;
    int warp_m = wid & 1;
    int warp_n = wid >> 1;

    int b = blockIdx.z;
    int row0 = blockIdx.y * 128;
    int col0 = blockIdx.x * 128;

    const __half* srcs[3] = {
        Ahi + ((size_t)b * NN + row0) * CF,
        Alo + ((size_t)b * NN + row0) * CF,
        Bhi + ((size_t)b * NN + col0) * CF };
    float* C = Cg + (size_t)b * NN * NN;

    float acc[4][4][4];
#pragma unroll
    for (int i = 0; i < 4; i++)
#pragma unroll
        for (int j = 0; j < 4; j++)
#pragma unroll
            for (int k = 0; k < 4; k++) acc[i][j][k] = 0.f;

    auto prefetch = [&](int c) {
        int kk = c * KCH;
        uint32_t stg = sbase + (c % PIPE4) * STG_BYTES;
#pragma unroll
        for (int it = 0; it < 6; it++) {
            int idx = it * 256 + tid;
            int t = idx >> 9;
            int w = idx & 511;
            int r = w >> 2, seg = w & 3;
            cp_async16(stg + (uint32_t)(t * TILE_BYTES + r * RSTR + seg * 16),
                       srcs[t] + (size_t)r * CF + kk + seg * 8);
        }
    };

    prefetch(0); CP_COMMIT();
    prefetch(1); CP_COMMIT();

    int a_row = (lane & 7) + ((lane >> 3) & 1) * 8;
    int a_k8  = (lane >> 4) * 8;
    int bg    = lane >> 3;
    int b_nat = bg >> 1;
    int b_k8  = (bg & 1) * 8;

    for (int c = 0; c < NCH; c++) {
        if (c + 2 < NCH) prefetch(c + 2);
        CP_COMMIT();
        CP_WAIT(2);
        __syncthreads();

        uint32_t stg = sbase + (c % PIPE4) * STG_BYTES;
        uint32_t sAh = stg, sAl = stg + TILE_BYTES, sBh = stg + 2 * TILE_BYTES;
#pragma unroll
        for (int k16 = 0; k16 < 2; k16++) {
            int kb = k16 * 16;
            uint32_t afh[4][4], afl[4][4];
#pragma unroll
            for (int am = 0; am < 4; am++) {
                uint32_t off = (uint32_t)((warp_m * 64 + am * 16 + a_row) * RSTR + (kb + a_k8) * 2);
                ldsm_x4(afh[am], sAh + off);
                ldsm_x4(afl[am], sAl + off);
            }
            uint32_t bfh[4][2];
#pragma unroll
            for (int bp = 0; bp < 2; bp++) {
                uint32_t boff = (uint32_t)((warp_n * 32 + (bp * 2 + b_nat) * 8 + (lane & 7)) * RSTR
                                           + (kb + b_k8) * 2);
                uint32_t r4[4];
                ldsm_x4(r4, sBh + boff);
                bfh[bp * 2 + 0][0] = r4[0]; bfh[bp * 2 + 0][1] = r4[1];
                bfh[bp * 2 + 1][0] = r4[2]; bfh[bp * 2 + 1][1] = r4[3];
            }
#pragma unroll
            for (int am = 0; am < 4; am++)
#pragma unroll
                for (int an = 0; an < 4; an++) {
                    mma16816(acc[am][an], afh[am], bfh[an]);
                    mma16816(acc[am][an], afl[am], bfh[an]);
                }
        }
    }

    int tr = lane >> 2, tc = (lane & 3) * 2;
#pragma unroll
    for (int am = 0; am < 4; am++)
#pragma unroll
        for (int an = 0; an < 4; an++) {
            int r = row0 + warp_m * 64 + am * 16 + tr;
            int cc = col0 + warp_n * 32 + an * 8 + tc;
            *(float2*)(C + (size_t)r * NN + cc) = make_float2(acc[am][an][0], acc[am][an][1]);
            *(float2*)(C + (size_t)(r + 8) * NN + cc) = make_float2(acc[am][an][2], acc[am][an][3]);
        }
}

// ---------------- row softmax, split-fp16 output ----------------
__global__ void softmax_split_rows(const float* __restrict__ Cmat,
                                   __half* __restrict__ Ahi, __half* __restrict__ Alo) {
    int row = blockIdx.x;
    const float* src = Cmat + (size_t)row * NN;
    __half* dh = Ahi + (size_t)row * NN;
    __half* dl = Alo + (size_t)row * NN;
    int tid = threadIdx.x;
    float v[4];
    float m = -1e30f;
#pragma unroll
    for (int i = 0; i < 4; i++) { v[i] = src[tid + i * 256]; m = fmaxf(m, v[i]); }
    __shared__ float red[256];
    red[tid] = m; __syncthreads();
    for (int s = 128; s > 0; s >>= 1) { if (tid < s) red[tid] = fmaxf(red[tid], red[tid + s]); __syncthreads(); }
    m = red[0]; __syncthreads();
    float ssum = 0.f;
#pragma unroll
    for (int i = 0; i < 4; i++) { v[i] = __expf(v[i] - m); ssum += v[i]; }
    red[tid] = ssum; __syncthreads();
    for (int s = 128; s > 0; s >>= 1) { if (tid < s) red[tid] += red[tid + s]; __syncthreads(); }
    float inv = 1.f / red[0];
#pragma unroll
    for (int i = 0; i < 4; i++) {
        float x = v[i] * inv;
        __half h = __float2half_rn(x);
        dh[tid + i * 256] = h;
        dl[tid + i * 256] = __float2half_rn(x - __half2float(h));
    }
}

// =====================================================================
// gemm_nn_mma: f_a = (Ah+Al) @ Bh^T
// =====================================================================
#define NKCH   (NN / KCH)
#define AT_BYTES (64 * RSTR)
#define BT_BYTES (128 * RSTR)
#define STG2_BYTES (2 * AT_BYTES + BT_BYTES)
#define GEMM2_SMEM (PIPE4 * STG2_BYTES)

__global__ __launch_bounds__(256) void gemm_nn_mma(
    const __half* __restrict__ Ahi, const __half* __restrict__ Alo,
    const __half* __restrict__ Bhi, float* __restrict__ Fg)
{
    extern __shared__ __align__(128) char smem[];
    uint32_t sbase = smem_u32(smem);
    int tid = threadIdx.x;
    int wid = tid >> 5, lane = tid & 31;
    int warp_m = wid & 1;
    int warp_n = wid >> 1;

    int b = blockIdx.y;
    int mrow0 = blockIdx.x * 64;

    const __half* Ah = Ahi + ((size_t)b * NN + mrow0) * NN;
    const __half* Al = Alo + ((size_t)b * NN + mrow0) * NN;
    const __half* Bh = Bhi + (size_t)b * 128 * NN;
    float* F = Fg + (size_t)b * NN * 128;

    float acc[2][4][4];
#pragma unroll
    for (int i = 0; i < 2; i++)
#pragma unroll
        for (int j = 0; j < 4; j++)
#pragma unroll
            for (int k = 0; k < 4; k++) acc[i][j][k] = 0.f;

    auto prefetch = [&](int c) {
        int kk = c * KCH;
        uint32_t stg = sbase + (c % PIPE4) * STG2_BYTES;
#pragma unroll
        for (int it = 0; it < 4; it++) {
            int idx = it * 256 + tid;
            if (idx < 512) {
                int pl = idx >> 8, w = idx & 255;
                int r = w >> 2, seg = w & 3;
                const __half* s = pl ? Al : Ah;
                cp_async16(stg + (uint32_t)(pl * AT_BYTES + r * RSTR + seg * 16),
                           s + (size_t)r * NN + kk + seg * 8);
            } else {
                int w = idx - 512;
                int r = w >> 2, seg = w & 3;
                cp_async16(stg + (uint32_t)(2 * AT_BYTES + r * RSTR + seg * 16),
                           Bh + (size_t)r * NN + kk + seg * 8);
            }
        }
    };

    prefetch(0); CP_COMMIT();
    prefetch(1); CP_COMMIT();

    int a_row = (lane & 7) + ((lane >> 3) & 1) * 8;
    int a_k8  = (lane >> 4) * 8;
    int bg    = lane >> 3;
    int b_nat = bg >> 1;
    int b_k8  = (bg & 1) * 8;

    for (int c = 0; c < NKCH; c++) {
        if (c + 2 < NKCH) prefetch(c + 2);
        CP_COMMIT();
        CP_WAIT(2);
        __syncthreads();

        uint32_t stg = sbase + (c % PIPE4) * STG2_BYTES;
        uint32_t sAh = stg, sAl = stg + AT_BYTES, sBh = stg + 2 * AT_BYTES;
#pragma unroll
        for (int k16 = 0; k16 < 2; k16++) {
            int kb = k16 * 16;
            uint32_t afh[2][4], afl[2][4];
#pragma unroll
            for (int am = 0; am < 2; am++) {
                uint32_t off = (uint32_t)((warp_m * 32 + am * 16 + a_row) * RSTR + (kb + a_k8) * 2);
                ldsm_x4(afh[am], sAh + off);
                ldsm_x4(afl[am], sAl + off);
            }
            uint32_t bfh[4][2];
#pragma unroll
            for (int bp = 0; bp < 2; bp++) {
                uint32_t boff = (uint32_t)((warp_n * 32 + (bp * 2 + b_nat) * 8 + (lane & 7)) * RSTR
                                           + (kb + b_k8) * 2);
                uint32_t r4[4];
                ldsm_x4(r4, sBh + boff);
                bfh[bp * 2 + 0][0] = r4[0]; bfh[bp * 2 + 0][1] = r4[1];
                bfh[bp * 2 + 1][0] = r4[2]; bfh[bp * 2 + 1][1] = r4[3];
            }
#pragma unroll
            for (int am = 0; am < 2; am++)
#pragma unroll
                for (int an = 0; an < 4; an++) {
                    mma16816(acc[am][an], afh[am], bfh[an]);
                    mma16816(acc[am][an], afl[am], bfh[an]);
                }
        }
    }

    int tr = lane >> 2, tc = (lane & 3) * 2;
#pragma unroll
    for (int am = 0; am < 2; am++)
#pragma unroll
        for (int an = 0; an < 4; an++) {
            int r = mrow0 + warp_m * 32 + am * 16 + tr;
            int cc = warp_n * 32 + an * 8 + tc;
            *(float2*)(F + (size_t)r * 128 + cc) = make_float2(acc[am][an][0], acc[am][an][1]);
            *(float2*)(F + (size_t)(r + 8) * 128 + cc) = make_float2(acc[am][an][2], acc[am][an][3]);
        }
}

// ------- templated 3x3 conv + bias + relu, NHWC, Cout split across blocks -------
template <int TILE, int STRIDE, int CIN, int COSPLIT>
__global__ void conv2d_relu_t(
    const float* __restrict__ in, const float* __restrict__ w,
    const float* __restrict__ bias, float* __restrict__ out,
    int Hin, int Win, int Hout, int Wout, int Cout, int pad)
{
    constexpr int SPANX = (TILE - 1) * STRIDE + 3;
    extern __shared__ float sm[];
    int b = blockIdx.z;
    int oy = blockIdx.y;
    int xt = blockIdx.x / COSPLIT;
    int cs = blockIdx.x % COSPLIT;
    int ox0 = xt * TILE;
    int co = cs * blockDim.x + threadIdx.x;

    int iy0 = oy * STRIDE - pad;
    int ix0 = ox0 * STRIDE - pad;
    constexpr int TOT = 3 * SPANX * CIN;
    for (int i = threadIdx.x; i < TOT; i += blockDim.x) {
        int ci = i % CIN; int rest = i / CIN;
        int xx = rest % SPANX; int r = rest / SPANX;
        int iy = iy0 + r, ix = ix0 + xx;
        float v = 0.f;
        if (iy >= 0 && iy < Hin && ix >= 0 && ix < Win)
            v = in[(((size_t)b * Hin + iy) * Win + ix) * CIN + ci];
        sm[(r * SPANX + xx) * CIN + ci] = v;
    }
    __syncthreads();

    float acc[TILE];
    float bv = bias[co];
#pragma unroll
    for (int p = 0; p < TILE; p++) acc[p] = bv;

#pragma unroll
    for (int r = 0; r < 3; r++)
#pragma unroll
        for (int kx = 0; kx < 3; kx++) {
#pragma unroll 8
            for (int ci = 0; ci < CIN; ci++) {
                float wv = w[(size_t)((r * 3 + kx) * CIN + ci) * Cout + co];
                const float* srow = &sm[(r * SPANX + kx) * CIN + ci];
#pragma unroll
                for (int p = 0; p < TILE; p++)
                    acc[p] += srow[(size_t)p * STRIDE * CIN] * wv;
            }
        }
#pragma unroll
    for (int p = 0; p < TILE; p++) {
        int ox = ox0 + p;
        out[(((size_t)b * Hout + oy) * Wout + ox) * Cout + co] = fmaxf(acc[p], 0.f);
    }
}

// ---- conv2: stride-2 3x3, Cin=64 -> 128, TRANSPOSED fp16, TILE=8 ----
__global__ void conv2_t_fp16(
    const float* __restrict__ in, const float* __restrict__ w,
    const float* __restrict__ bias, __half* __restrict__ out_hi)
{
    constexpr int TILE = 8, STRIDE = 2, SPANX = 17, CIN = 64, COUT = 128;
    extern __shared__ float sm[];           // [3][17][64]
    int b = blockIdx.z;
    int oy = blockIdx.y;
    int ox0 = blockIdx.x * TILE;
    int co = threadIdx.x;

    int iy0 = oy * STRIDE;
    int ix0 = ox0 * STRIDE;
    constexpr int TOT = 3 * SPANX * CIN;
    for (int i = threadIdx.x; i < TOT; i += COUT) {
        int ci = i % CIN; int rest = i / CIN;
        int xx = rest % SPANX; int r = rest / SPANX;
        int iy = iy0 + r, ix = ix0 + xx;
        float v = 0.f;
        if (iy < 64 && ix < 64)
            v = in[(((size_t)b * 64 + iy) * 64 + ix) * CIN + ci];
        sm[(r * SPANX + xx) * CIN + ci] = v;
    }
    __syncthreads();

    float acc[TILE];
    float bv = bias[co];
#pragma unroll
    for (int p = 0; p < TILE; p++) acc[p] = bv;

#pragma unroll
    for (int r = 0; r < 3; r++)
#pragma unroll
        for (int kx = 0; kx < 3; kx++) {
#pragma unroll 8
            for (int ci = 0; ci < CIN; ci++) {
                float wv = w[(size_t)((r * 3 + kx) * CIN + ci) * COUT + co];
                const float* srow = &sm[(r * SPANX + kx) * CIN + ci];
#pragma unroll
                for (int p = 0; p < TILE; p++)
                    acc[p] += srow[(size_t)p * STRIDE * CIN] * wv;
            }
        }
    __half* dh = out_hi + ((size_t)b * COUT + co) * NN + oy * 32 + ox0;
#pragma unroll
    for (int p = 0; p < TILE; p++)
        dh[p] = __float2half_rn(fmaxf(acc[p], 0.f));
}

// ---------------- maxpool: 2-phase ----------------
__global__ void maxpool_p1(const float* __restrict__ t, float* __restrict__ mpp) {
    int b = blockIdx.z;
    int ns = blockIdx.y;
    int c = blockIdx.x * 256 + threadIdx.x;
    if (c >= CF) return;
    const float* src = t + ((size_t)b * NN + ns * 128) * CF + c;
    float m = -1e30f;
#pragma unroll 8
    for (int n = 0; n < 128; n++) m = fmaxf(m, src[(size_t)n * CF]);
    mpp[((size_t)ns * NB + b) * CF + c] = m;
}
__global__ void maxpool_p2(const float* __restrict__ mpp, float* __restrict__ mp) {
    int b = blockIdx.y;
    int c = blockIdx.x * 256 + threadIdx.x;
    if (c >= CF) return;
    float m = -1e30f;
#pragma unroll
    for (int ns = 0; ns < 8; ns++) m = fmaxf(m, mpp[((size_t)ns * NB + b) * CF + c]);
    mp[b * CF + c] = m;
}

// ---------------- dense1: K-split partials + reduce ----------------
__global__ void dense1_p1(const float* __restrict__ mp, const float* __restrict__ w,
                          float* __restrict__ d1p) {
    int ks = blockIdx.x;                    // 0..7
    int b = blockIdx.y;
    int j = threadIdx.x;                    // 512
    __shared__ float sm[248];
    for (int k = threadIdx.x; k < 248; k += 512) sm[k] = mp[b * CF + ks * 248 + k];
    __syncthreads();
    float s = 0.f;
#pragma unroll 8
    for (int k = 0; k < 248; k++) s += sm[k] * w[(size_t)(ks * 248 + k) * 512 + j];
    d1p[((size_t)ks * NB + b) * 512 + j] = s;
}
__global__ void dense1_p2(const float* __restrict__ d1p, const float* __restrict__ bias,
                          float* __restrict__ g1) {
    int b = blockIdx.x;
    int j = threadIdx.x;
    float s = bias[j];
#pragma unroll
    for (int ks = 0; ks < 8; ks++) s += d1p[((size_t)ks * NB + b) * 512 + j];
    g1[b * 512 + j] = fmaxf(s, 0.f);
}

// ---------------- dense2 logits (j-split) + softmax ----------------
__global__ void dense2_p1(const float* __restrict__ g1, const float* __restrict__ w,
                          const float* __restrict__ bias, float* __restrict__ logits) {
    int jb = blockIdx.x;                    // 0..7
    int b = blockIdx.y;
    int j = jb * 128 + threadIdx.x;
    __shared__ float sg[512];
    for (int k = threadIdx.x; k < 512; k += 128) sg[k] = g1[b * 512 + k];
    __syncthreads();
    if (j >= NCLS) return;
    float s = bias[j];
#pragma unroll 8
    for (int k = 0; k < 512; k++) s += sg[k] * w[(size_t)k * NCLS + j];
    logits[b * NCLS + j] = s;
}
__global__ void softmax1000(const float* __restrict__ logits, float* __restrict__ out) {
    int b = blockIdx.x;
    const float* src = logits + b * NCLS;
    int tid = threadIdx.x;                  // 256
    __shared__ float red[256];
    float m = -1e30f;
    for (int j = tid; j < NCLS; j += 256) m = fmaxf(m, src[j]);
    red[tid] = m; __syncthreads();
    for (int s = 128; s > 0; s >>= 1) { if (tid < s) red[tid] = fmaxf(red[tid], red[tid + s]); __syncthreads(); }
    m = red[0]; __syncthreads();
    float ssum = 0.f;
    for (int j = tid; j < NCLS; j += 256) ssum += __expf(src[j] - m);
    red[tid] = ssum; __syncthreads();
    for (int s = 128; s > 0; s >>= 1) { if (tid < s) red[tid] += red[tid + s]; __syncthreads(); }
    float inv = 1.f / red[0];
    for (int j = tid; j < NCLS; j += 256) out[b * NCLS + j] = __expf(src[j] - m) * inv;
}

// ---------------- launcher ----------------
extern "C" void kernel_launch(void* const* d_in, const int* in_sizes, int n_in,
                              void* d_out, int out_size) {
    const float* t_lum  = (const float*)d_in[0];
    const float* r_lum  = (const float*)d_in[1];
    const float* r_ab   = (const float*)d_in[2];
    const float* w_rab1 = (const float*)d_in[3];
    const float* b_rab1 = (const float*)d_in[4];
    const float* w_rab2 = (const float*)d_in[5];
    const float* b_rab2 = (const float*)d_in[6];
    const float* w_fa1  = (const float*)d_in[7];
    const float* b_fa1  = (const float*)d_in[8];
    const float* w_fa2  = (const float*)d_in[9];
    const float* b_fa2  = (const float*)d_in[10];
    const float* w_fa3  = (const float*)d_in[11];
    const float* b_fa3  = (const float*)d_in[12];
    const float* w_d1   = (const float*)d_in[13];
    const float* b_d1   = (const float*)d_in[14];
    const float* w_d2   = (const float*)d_in[15];
    const float* b_d2   = (const float*)d_in[16];

    __half *tnh, *tnl, *rnh, *Ahi, *Alo, *fTh;
    float *frab1, *fa, *mpp, *mp, *d1p, *g1, *logits;
    cudaGetSymbolAddress((void**)&tnh,    g_tn_hi);
    cudaGetSymbolAddress((void**)&tnl,    g_tn_lo);
    cudaGetSymbolAddress((void**)&rnh,    g_rn_hi);
    cudaGetSymbolAddress((void**)&Ahi,    g_A_hi);
    cudaGetSymbolAddress((void**)&Alo,    g_A_lo);
    cudaGetSymbolAddress((void**)&fTh,    g_frabT_hi);
    cudaGetSymbolAddress((void**)&frab1,  g_frab1);
    cudaGetSymbolAddress((void**)&fa,     g_fa);
    cudaGetSymbolAddress((void**)&mpp,    g_mpp);
    cudaGetSymbolAddress((void**)&mp,     g_mp);
    cudaGetSymbolAddress((void**)&d1p,    g_d1p);
    cudaGetSymbolAddress((void**)&g1,     g_g1);
    cudaGetSymbolAddress((void**)&logits, g_logits);

    cudaFuncSetAttribute(gemm_nt_mma, cudaFuncAttributeMaxDynamicSharedMemorySize, GEMM_SMEM);
    cudaFuncSetAttribute(gemm_nn_mma, cudaFuncAttributeMaxDynamicSharedMemorySize, GEMM2_SMEM);

    float* out  = (float*)d_out;
    float* Cmat = out + 8000;
    float* s1   = out + 8396608;
    float* s2   = out + 8462144;
    float* s3   = out + 8593216;

    // 1,2: normalize + fp16 split
    normalize_split_hl<<<NB * NN, 256>>>(t_lum, tnh, tnl);
    normalize_split_h<<<NB * NN, 256>>>(r_lum, rnh);

    // 3: chroma conv1
    conv2d_relu_t<16, 1, 2, 1><<<dim3(4, 64, NB), 64, 3 * 18 * 2 * 4>>>(
        r_ab, w_rab1, b_rab1, frab1, 64, 64, 64, 64, 64, 1);

    // 4: cost volume (profile slot)
    gemm_nt_mma<<<dim3(8, 8, NB), 256, GEMM_SMEM>>>(tnh, tnl, rnh, Cmat);

    // 5: chroma conv2 -> transposed fp16, TILE=8 (1024 blocks)
    conv2_t_fp16<<<dim3(4, 32, NB), 128, 3 * 17 * 64 * 4>>>(
        frab1, w_rab2, b_rab2, fTh);

    // 6: softmax -> split-fp16
    softmax_split_rows<<<NB * NN, 256>>>(Cmat, Ahi, Alo);

    // 7: attention
    gemm_nn_mma<<<dim3(NN / 64, NB), 256, GEMM2_SMEM>>>(Ahi, Alo, fTh, fa);

    // 8-10: pyramid (smaller tiles / cout split for parallelism)
    conv2d_relu_t<4, 2, 128, 1><<<dim3(4, 16, NB), 128, 3 * 9 * 128 * 4>>>(
        fa, w_fa1, b_fa1, s3, 32, 32, 16, 16, 128, 0);
    conv2d_relu_t<4, 2, 128, 1><<<dim3(2, 8, NB), 256, 3 * 9 * 128 * 4>>>(
        s3, w_fa2, b_fa2, s2, 16, 16, 8, 8, 256, 0);
    conv2d_relu_t<2, 2, 256, 2><<<dim3(4, 4, NB), 256, 3 * 5 * 256 * 4>>>(
        s2, w_fa3, b_fa3, s1, 8, 8, 4, 4, 512, 0);

    // 11-12: maxpool 2-phase
    maxpool_p1<<<dim3(8, 8, NB), 256>>>(t_lum, mpp);
    maxpool_p2<<<dim3(8, NB), 256>>>(mpp, mp);

    // 13-14: dense1 2-phase
    dense1_p1<<<dim3(8, NB), 512>>>(mp, w_d1, d1p);
    dense1_p2<<<NB, 512>>>(d1p, b_d1, g1);

    // 15-16: dense2 + softmax
    dense2_p1<<<dim3(8, NB), 128>>>(g1, w_d2, b_d2, logits);
    softmax1000<<<NB, 256>>>(logits, out);
}

// round 9
// speedup vs baseline: 3.1854x; 1.0009x over previous
#include <cuda_runtime.h>
#include <cuda_fp16.h>
#include <math.h>
#include <stdint.h>

#define CF   1984
#define NB   8
#define NN   1024    // h*w = 32*32
#define NCLS 1000

// ---------------- scratch (static device globals; no allocation) ----------------
__device__ __half g_tn_hi[NB * NN * CF];
__device__ __half g_tn_lo[NB * NN * CF];
__device__ __half g_rn_hi[NB * NN * CF];
__device__ __half g_A_hi[NB * NN * NN];
__device__ __half g_A_lo[NB * NN * NN];
__device__ __half g_frabT_hi[NB * 128 * NN];
__device__ float g_frab1[NB * 64 * 64 * 64];
__device__ float g_fa[NB * NN * 128];
__device__ float g_mpp[8 * NB * CF];
__device__ float g_mp[NB * CF];
__device__ float g_d1p[8 * NB * 512];
__device__ float g_g1[NB * 512];
__device__ float g_logits[NB * NCLS];

// ============================ helpers ============================
__device__ __forceinline__ uint32_t smem_u32(const void* p) {
    uint32_t a;
    asm("{ .reg .u64 t; cvta.to.shared.u64 t, %1; cvt.u32.u64 %0, t; }" : "=r"(a) : "l"(p));
    return a;
}
__device__ __forceinline__ void cp_async16(uint32_t dst, const void* src) {
    asm volatile("cp.async.cg.shared.global [%0], [%1], 16;" :: "r"(dst), "l"(src));
}
#define CP_COMMIT() asm volatile("cp.async.commit_group;" ::: "memory")
#define CP_WAIT(n)  asm volatile("cp.async.wait_group %0;" :: "n"(n) : "memory")

__device__ __forceinline__ void ldsm_x4(uint32_t* r, uint32_t addr) {
    asm volatile("ldmatrix.sync.aligned.m8n8.x4.shared.b16 {%0,%1,%2,%3}, [%4];"
                 : "=r"(r[0]), "=r"(r[1]), "=r"(r[2]), "=r"(r[3]) : "r"(addr));
}
__device__ __forceinline__ void mma16816(float* d, const uint32_t* a, const uint32_t* b) {
    asm volatile(
        "mma.sync.aligned.m16n8k16.row.col.f32.f16.f16.f32 "
        "{%0,%1,%2,%3}, {%4,%5,%6,%7}, {%8,%9}, {%0,%1,%2,%3};"
        : "+f"(d[0]), "+f"(d[1]), "+f"(d[2]), "+f"(d[3])
        : "r"(a[0]), "r"(a[1]), "r"(a[2]), "r"(a[3]), "r"(b[0]), "r"(b[1]));
}

// ---------------- normalize + fp16 hi/lo split (half2 stores) ----------------
__global__ void normalize_split_hl(const float* __restrict__ in,
                                   __half* __restrict__ hi, __half* __restrict__ lo) {
    int row = blockIdx.x;
    const float* src = in + (size_t)row * CF;
    __half* dh = hi + (size_t)row * CF;
    __half* dl = lo + (size_t)row * CF;
    float2 v[4];
    float ss = 0.f;
#pragma unroll
    for (int i = 0; i < 4; i++) {
        int c2 = (threadIdx.x + i * 256) * 2;
        if (c2 < CF) { v[i] = *(const float2*)(src + c2); ss += v[i].x * v[i].x + v[i].y * v[i].y; }
        else v[i] = make_float2(0.f, 0.f);
    }
    __shared__ float red[256];
    red[threadIdx.x] = ss; __syncthreads();
    for (int s = 128; s > 0; s >>= 1) {
        if (threadIdx.x < s) red[threadIdx.x] += red[threadIdx.x + s];
        __syncthreads();
    }
    float inv = 1.f / (sqrtf(red[0]) + 1e-6f);
#pragma unroll
    for (int i = 0; i < 4; i++) {
        int c2 = (threadIdx.x + i * 256) * 2;
        if (c2 < CF) {
            float x0 = v[i].x * inv, x1 = v[i].y * inv;
            __half h0 = __float2half_rn(x0), h1 = __float2half_rn(x1);
            *(__half2*)(dh + c2) = __halves2half2(h0, h1);
            *(__half2*)(dl + c2) = __halves2half2(
                __float2half_rn(x0 - __half2float(h0)), __float2half_rn(x1 - __half2float(h1)));
        }
    }
}
__global__ void normalize_split_h(const float* __restrict__ in, __half* __restrict__ hi) {
    int row = blockIdx.x;
    const float* src = in + (size_t)row * CF;
    __half* dh = hi + (size_t)row * CF;
    float2 v[4];
    float ss = 0.f;
#pragma unroll
    for (int i = 0; i < 4; i++) {
        int c2 = (threadIdx.x + i * 256) * 2;
        if (c2 < CF) { v[i] = *(const float2*)(src + c2); ss += v[i].x * v[i].x + v[i].y * v[i].y; }
        else v[i] = make_float2(0.f, 0.f);
    }
    __shared__ float red[256];
    red[threadIdx.x] = ss; __syncthreads();
    for (int s = 128; s > 0; s >>= 1) {
        if (threadIdx.x < s) red[threadIdx.x] += red[threadIdx.x + s];
        __syncthreads();
    }
    float inv = 1.f / (sqrtf(red[0]) + 1e-6f);
#pragma unroll
    for (int i = 0; i < 4; i++) {
        int c2 = (threadIdx.x + i * 256) * 2;
        if (c2 < CF)
            *(__half2*)(dh + c2) = __halves2half2(
                __float2half_rn(v[i].x * inv), __float2half_rn(v[i].y * inv));
    }
}

// =====================================================================
// gemm_nt_mma: C = Ah*Bh^T + Al*Bh^T  (2-term fp16 split)
// PIPE=3, 2 CTAs/SM; prefetch AFTER sync (stage(c+2)==stage(c-1) freed by sync)
// =====================================================================
#define KCH    32
#define NCH    (CF / KCH)        // 62
#define RSTR   80
#define TILE_BYTES (128 * RSTR)          // 10240
#define STG_BYTES  (3 * TILE_BYTES)      // 30720
#define PIPE3  3
#define GEMM_SMEM (PIPE3 * STG_BYTES)    // 92160

__global__ __launch_bounds__(256, 2) void gemm_nt_mma(
    const __half* __restrict__ Ahi, const __half* __restrict__ Alo,
    const __half* __restrict__ Bhi, float* __restrict__ Cg)
{
    extern __shared__ __align__(128) char smem[];
    uint32_t sbase = smem_u32(smem);
    int tid = threadIdx.x;
    int wid = tid >> 5, lane = tid & 31;
    int warp_m = wid & 1;
    int warp_n = wid >> 1;

    int b = blockIdx.z;
    int row0 = blockIdx.y * 128;
    int col0 = blockIdx.x * 128;

    const __half* srcs[3] = {
        Ahi + ((size_t)b * NN + row0) * CF,
        Alo + ((size_t)b * NN + row0) * CF,
        Bhi + ((size_t)b * NN + col0) * CF };
    float* C = Cg + (size_t)b * NN * NN;

    float acc[4][4][4];
#pragma unroll
    for (int i = 0; i < 4; i++)
#pragma unroll
        for (int j = 0; j < 4; j++)
#pragma unroll
            for (int k = 0; k < 4; k++) acc[i][j][k] = 0.f;

    auto prefetch = [&](int c) {
        int kk = c * KCH;
        uint32_t stg = sbase + (c % PIPE3) * STG_BYTES;
#pragma unroll
        for (int it = 0; it < 6; it++) {
            int idx = it * 256 + tid;
            int t = idx >> 9;
            int w = idx & 511;
            int r = w >> 2, seg = w & 3;
            cp_async16(stg + (uint32_t)(t * TILE_BYTES + r * RSTR + seg * 16),
                       srcs[t] + (size_t)r * CF + kk + seg * 8);
        }
    };

    prefetch(0); CP_COMMIT();
    prefetch(1); CP_COMMIT();

    int a_row = (lane & 7) + ((lane >> 3) & 1) * 8;
    int a_k8  = (lane >> 4) * 8;
    int bg    = lane >> 3;
    int b_nat = bg >> 1;
    int b_k8  = (bg & 1) * 8;

    for (int c = 0; c < NCH; c++) {
        CP_WAIT(1);          // chunk c arrived (c+1 may be pending)
        __syncthreads();     // all warps done with chunk c-1 -> its stage is free
        if (c + 2 < NCH) { prefetch(c + 2); CP_COMMIT(); }

        uint32_t stg = sbase + (c % PIPE3) * STG_BYTES;
        uint32_t sAh = stg, sAl = stg + TILE_BYTES, sBh = stg + 2 * TILE_BYTES;
#pragma unroll
        for (int k16 = 0; k16 < 2; k16++) {
            int kb = k16 * 16;
            uint32_t afh[4][4], afl[4][4];
#pragma unroll
            for (int am = 0; am < 4; am++) {
                uint32_t off = (uint32_t)((warp_m * 64 + am * 16 + a_row) * RSTR + (kb + a_k8) * 2);
                ldsm_x4(afh[am], sAh + off);
                ldsm_x4(afl[am], sAl + off);
            }
            uint32_t bfh[4][2];
#pragma unroll
            for (int bp = 0; bp < 2; bp++) {
                uint32_t boff = (uint32_t)((warp_n * 32 + (bp * 2 + b_nat) * 8 + (lane & 7)) * RSTR
                                           + (kb + b_k8) * 2);
                uint32_t r4[4];
                ldsm_x4(r4, sBh + boff);
                bfh[bp * 2 + 0][0] = r4[0]; bfh[bp * 2 + 0][1] = r4[1];
                bfh[bp * 2 + 1][0] = r4[2]; bfh[bp * 2 + 1][1] = r4[3];
            }
#pragma unroll
            for (int am = 0; am < 4; am++)
#pragma unroll
                for (int an = 0; an < 4; an++) {
                    mma16816(acc[am][an], afh[am], bfh[an]);
                    mma16816(acc[am][an], afl[am], bfh[an]);
                }
        }
        __syncthreads();     // finish reading stage before next iter's prefetch reuses it
    }

    int tr = lane >> 2, tc = (lane & 3) * 2;
#pragma unroll
    for (int am = 0; am < 4; am++)
#pragma unroll
        for (int an = 0; an < 4; an++) {
            int r = row0 + warp_m * 64 + am * 16 + tr;
            int cc = col0 + warp_n * 32 + an * 8 + tc;
            *(float2*)(C + (size_t)r * NN + cc) = make_float2(acc[am][an][0], acc[am][an][1]);
            *(float2*)(C + (size_t)(r + 8) * NN + cc) = make_float2(acc[am][an][2], acc[am][an][3]);
        }
}

// ---------------- row softmax, split-fp16 half2 output ----------------
__global__ void softmax_split_rows(const float* __restrict__ Cmat,
                                   __half* __restrict__ Ahi, __half* __restrict__ Alo) {
    int row = blockIdx.x;
    const float* src = Cmat + (size_t)row * NN;
    __half* dh = Ahi + (size_t)row * NN;
    __half* dl = Alo + (size_t)row * NN;
    int tid = threadIdx.x;
    float2 v[2];
    float m = -1e30f;
#pragma unroll
    for (int i = 0; i < 2; i++) {
        int c2 = (tid + i * 256) * 2;
        v[i] = *(const float2*)(src + c2);
        m = fmaxf(m, fmaxf(v[i].x, v[i].y));
    }
    __shared__ float red[256];
    red[tid] = m; __syncthreads();
    for (int s = 128; s > 0; s >>= 1) { if (tid < s) red[tid] = fmaxf(red[tid], red[tid + s]); __syncthreads(); }
    m = red[0]; __syncthreads();
    float ssum = 0.f;
#pragma unroll
    for (int i = 0; i < 2; i++) {
        v[i].x = __expf(v[i].x - m); v[i].y = __expf(v[i].y - m);
        ssum += v[i].x + v[i].y;
    }
    red[tid] = ssum; __syncthreads();
    for (int s = 128; s > 0; s >>= 1) { if (tid < s) red[tid] += red[tid + s]; __syncthreads(); }
    float inv = 1.f / red[0];
#pragma unroll
    for (int i = 0; i < 2; i++) {
        int c2 = (tid + i * 256) * 2;
        float x0 = v[i].x * inv, x1 = v[i].y * inv;
        __half h0 = __float2half_rn(x0), h1 = __float2half_rn(x1);
        *(__half2*)(dh + c2) = __halves2half2(h0, h1);
        *(__half2*)(dl + c2) = __halves2half2(
            __float2half_rn(x0 - __half2float(h0)), __float2half_rn(x1 - __half2float(h1)));
    }
}

// =====================================================================
// gemm_nn_mma: f_a = (Ah+Al) @ Bh^T  (unchanged schedule, PIPE=4)
// =====================================================================
#define NKCH   (NN / KCH)
#define AT_BYTES (64 * RSTR)
#define BT_BYTES (128 * RSTR)
#define STG2_BYTES (2 * AT_BYTES + BT_BYTES)
#define PIPE4  4
#define GEMM2_SMEM (PIPE4 * STG2_BYTES)

__global__ __launch_bounds__(256) void gemm_nn_mma(
    const __half* __restrict__ Ahi, const __half* __restrict__ Alo,
    const __half* __restrict__ Bhi, float* __restrict__ Fg)
{
    extern __shared__ __align__(128) char smem[];
    uint32_t sbase = smem_u32(smem);
    int tid = threadIdx.x;
    int wid = tid >> 5, lane = tid & 31;
    int warp_m = wid & 1;
    int warp_n = wid >> 1;

    int b = blockIdx.y;
    int mrow0 = blockIdx.x * 64;

    const __half* Ah = Ahi + ((size_t)b * NN + mrow0) * NN;
    const __half* Al = Alo + ((size_t)b * NN + mrow0) * NN;
    const __half* Bh = Bhi + (size_t)b * 128 * NN;
    float* F = Fg + (size_t)b * NN * 128;

    float acc[2][4][4];
#pragma unroll
    for (int i = 0; i < 2; i++)
#pragma unroll
        for (int j = 0; j < 4; j++)
#pragma unroll
            for (int k = 0; k < 4; k++) acc[i][j][k] = 0.f;

    auto prefetch = [&](int c) {
        int kk = c * KCH;
        uint32_t stg = sbase + (c % PIPE4) * STG2_BYTES;
#pragma unroll
        for (int it = 0; it < 4; it++) {
            int idx = it * 256 + tid;
            if (idx < 512) {
                int pl = idx >> 8, w = idx & 255;
                int r = w >> 2, seg = w & 3;
                const __half* s = pl ? Al : Ah;
                cp_async16(stg + (uint32_t)(pl * AT_BYTES + r * RSTR + seg * 16),
                           s + (size_t)r * NN + kk + seg * 8);
            } else {
                int w = idx - 512;
                int r = w >> 2, seg = w & 3;
                cp_async16(stg + (uint32_t)(2 * AT_BYTES + r * RSTR + seg * 16),
                           Bh + (size_t)r * NN + kk + seg * 8);
            }
        }
    };

    prefetch(0); CP_COMMIT();
    prefetch(1); CP_COMMIT();

    int a_row = (lane & 7) + ((lane >> 3) & 1) * 8;
    int a_k8  = (lane >> 4) * 8;
    int bg    = lane >> 3;
    int b_nat = bg >> 1;
    int b_k8  = (bg & 1) * 8;

    for (int c = 0; c < NKCH; c++) {
        if (c + 2 < NKCH) prefetch(c + 2);
        CP_COMMIT();
        CP_WAIT(2);
        __syncthreads();

        uint32_t stg = sbase + (c % PIPE4) * STG2_BYTES;
        uint32_t sAh = stg, sAl = stg + AT_BYTES, sBh = stg + 2 * AT_BYTES;
#pragma unroll
        for (int k16 = 0; k16 < 2; k16++) {
            int kb = k16 * 16;
            uint32_t afh[2][4], afl[2][4];
#pragma unroll
            for (int am = 0; am < 2; am++) {
                uint32_t off = (uint32_t)((warp_m * 32 + am * 16 + a_row) * RSTR + (kb + a_k8) * 2);
                ldsm_x4(afh[am], sAh + off);
                ldsm_x4(afl[am], sAl + off);
            }
            uint32_t bfh[4][2];
#pragma unroll
            for (int bp = 0; bp < 2; bp++) {
                uint32_t boff = (uint32_t)((warp_n * 32 + (bp * 2 + b_nat) * 8 + (lane & 7)) * RSTR
                                           + (kb + b_k8) * 2);
                uint32_t r4[4];
                ldsm_x4(r4, sBh + boff);
                bfh[bp * 2 + 0][0] = r4[0]; bfh[bp * 2 + 0][1] = r4[1];
                bfh[bp * 2 + 1][0] = r4[2]; bfh[bp * 2 + 1][1] = r4[3];
            }
#pragma unroll
            for (int am = 0; am < 2; am++)
#pragma unroll
                for (int an = 0; an < 4; an++) {
                    mma16816(acc[am][an], afh[am], bfh[an]);
                    mma16816(acc[am][an], afl[am], bfh[an]);
                }
        }
        __syncthreads();
    }

    int tr = lane >> 2, tc = (lane & 3) * 2;
#pragma unroll
    for (int am = 0; am < 2; am++)
#pragma unroll
        for (int an = 0; an < 4; an++) {
            int r = mrow0 + warp_m * 32 + am * 16 + tr;
            int cc = warp_n * 32 + an * 8 + tc;
            *(float2*)(F + (size_t)r * 128 + cc) = make_float2(acc[am][an][0], acc[am][an][1]);
            *(float2*)(F + (size_t)(r + 8) * 128 + cc) = make_float2(acc[am][an][2], acc[am][an][3]);
        }
}

// ------- templated 3x3 conv + bias + relu, NHWC, Cout split across blocks -------
template <int TILE, int STRIDE, int CIN, int COSPLIT>
__global__ void conv2d_relu_t(
    const float* __restrict__ in, const float* __restrict__ w,
    const float* __restrict__ bias, float* __restrict__ out,
    int Hin, int Win, int Hout, int Wout, int Cout, int pad)
{
    constexpr int SPANX = (TILE - 1) * STRIDE + 3;
    extern __shared__ float sm[];
    int b = blockIdx.z;
    int oy = blockIdx.y;
    int xt = blockIdx.x / COSPLIT;
    int cs = blockIdx.x % COSPLIT;
    int ox0 = xt * TILE;
    int co = cs * blockDim.x + threadIdx.x;

    int iy0 = oy * STRIDE - pad;
    int ix0 = ox0 * STRIDE - pad;
    constexpr int TOT = 3 * SPANX * CIN;
    for (int i = threadIdx.x; i < TOT; i += blockDim.x) {
        int ci = i % CIN; int rest = i / CIN;
        int xx = rest % SPANX; int r = rest / SPANX;
        int iy = iy0 + r, ix = ix0 + xx;
        float v = 0.f;
        if (iy >= 0 && iy < Hin && ix >= 0 && ix < Win)
            v = in[(((size_t)b * Hin + iy) * Win + ix) * CIN + ci];
        sm[(r * SPANX + xx) * CIN + ci] = v;
    }
    __syncthreads();

    float acc[TILE];
    float bv = bias[co];
#pragma unroll
    for (int p = 0; p < TILE; p++) acc[p] = bv;

#pragma unroll
    for (int r = 0; r < 3; r++)
#pragma unroll
        for (int kx = 0; kx < 3; kx++) {
#pragma unroll 8
            for (int ci = 0; ci < CIN; ci++) {
                float wv = w[(size_t)((r * 3 + kx) * CIN + ci) * Cout + co];
                const float* srow = &sm[(r * SPANX + kx) * CIN + ci];
#pragma unroll
                for (int p = 0; p < TILE; p++)
                    acc[p] += srow[(size_t)p * STRIDE * CIN] * wv;
            }
        }
#pragma unroll
    for (int p = 0; p < TILE; p++) {
        int ox = ox0 + p;
        out[(((size_t)b * Hout + oy) * Wout + ox) * Cout + co] = fmaxf(acc[p], 0.f);
    }
}

// ---- conv2: stride-2 3x3, Cin=64 -> 128, TRANSPOSED fp16 ----
__global__ void conv2_t_fp16(
    const float* __restrict__ in, const float* __restrict__ w,
    const float* __restrict__ bias, __half* __restrict__ out_hi)
{
    constexpr int TILE = 8, STRIDE = 2, SPANX = 17, CIN = 64, COUT = 128;
    extern __shared__ float sm[];
    int b = blockIdx.z;
    int oy = blockIdx.y;
    int ox0 = blockIdx.x * TILE;
    int co = threadIdx.x;

    int iy0 = oy * STRIDE;
    int ix0 = ox0 * STRIDE;
    constexpr int TOT = 3 * SPANX * CIN;
    for (int i = threadIdx.x; i < TOT; i += COUT) {
        int ci = i % CIN; int rest = i / CIN;
        int xx = rest % SPANX; int r = rest / SPANX;
        int iy = iy0 + r, ix = ix0 + xx;
        float v = 0.f;
        if (iy < 64 && ix < 64)
            v = in[(((size_t)b * 64 + iy) * 64 + ix) * CIN + ci];
        sm[(r * SPANX + xx) * CIN + ci] = v;
    }
    __syncthreads();

    float acc[TILE];
    float bv = bias[co];
#pragma unroll
    for (int p = 0; p < TILE; p++) acc[p] = bv;

#pragma unroll
    for (int r = 0; r < 3; r++)
#pragma unroll
        for (int kx = 0; kx < 3; kx++) {
#pragma unroll 8
            for (int ci = 0; ci < CIN; ci++) {
                float wv = w[(size_t)((r * 3 + kx) * CIN + ci) * COUT + co];
                const float* srow = &sm[(r * SPANX + kx) * CIN + ci];
#pragma unroll
                for (int p = 0; p < TILE; p++)
                    acc[p] += srow[(size_t)p * STRIDE * CIN] * wv;
            }
        }
    __half* dh = out_hi + ((size_t)b * COUT + co) * NN + oy * 32 + ox0;
#pragma unroll
    for (int p = 0; p < TILE; p++)
        dh[p] = __float2half_rn(fmaxf(acc[p], 0.f));
}

// ---------------- maxpool: 2-phase ----------------
__global__ void maxpool_p1(const float* __restrict__ t, float* __restrict__ mpp) {
    int b = blockIdx.z;
    int ns = blockIdx.y;
    int c = blockIdx.x * 256 + threadIdx.x;
    if (c >= CF) return;
    const float* src = t + ((size_t)b * NN + ns * 128) * CF + c;
    float m = -1e30f;
#pragma unroll 8
    for (int n = 0; n < 128; n++) m = fmaxf(m, src[(size_t)n * CF]);
    mpp[((size_t)ns * NB + b) * CF + c] = m;
}
__global__ void maxpool_p2(const float* __restrict__ mpp, float* __restrict__ mp) {
    int b = blockIdx.y;
    int c = blockIdx.x * 256 + threadIdx.x;
    if (c >= CF) return;
    float m = -1e30f;
#pragma unroll
    for (int ns = 0; ns < 8; ns++) m = fmaxf(m, mpp[((size_t)ns * NB + b) * CF + c]);
    mp[b * CF + c] = m;
}

// ---------------- dense1: K-split partials + reduce ----------------
__global__ void dense1_p1(const float* __restrict__ mp, const float* __restrict__ w,
                          float* __restrict__ d1p) {
    int ks = blockIdx.x;
    int b = blockIdx.y;
    int j = threadIdx.x;
    __shared__ float sm[248];
    for (int k = threadIdx.x; k < 248; k += 512) sm[k] = mp[b * CF + ks * 248 + k];
    __syncthreads();
    float s = 0.f;
#pragma unroll 8
    for (int k = 0; k < 248; k++) s += sm[k] * w[(size_t)(ks * 248 + k) * 512 + j];
    d1p[((size_t)ks * NB + b) * 512 + j] = s;
}
__global__ void dense1_p2(const float* __restrict__ d1p, const float* __restrict__ bias,
                          float* __restrict__ g1) {
    int b = blockIdx.x;
    int j = threadIdx.x;
    float s = bias[j];
#pragma unroll
    for (int ks = 0; ks < 8; ks++) s += d1p[((size_t)ks * NB + b) * 512 + j];
    g1[b * 512 + j] = fmaxf(s, 0.f);
}

// ---------------- dense2 logits (j-split) + softmax ----------------
__global__ void dense2_p1(const float* __restrict__ g1, const float* __restrict__ w,
                          const float* __restrict__ bias, float* __restrict__ logits) {
    int jb = blockIdx.x;
    int b = blockIdx.y;
    int j = jb * 128 + threadIdx.x;
    __shared__ float sg[512];
    for (int k = threadIdx.x; k < 512; k += 128) sg[k] = g1[b * 512 + k];
    __syncthreads();
    if (j >= NCLS) return;
    float s = bias[j];
#pragma unroll 8
    for (int k = 0; k < 512; k++) s += sg[k] * w[(size_t)k * NCLS + j];
    logits[b * NCLS + j] = s;
}
__global__ void softmax1000(const float* __restrict__ logits, float* __restrict__ out) {
    int b = blockIdx.x;
    const float* src = logits + b * NCLS;
    int tid = threadIdx.x;
    __shared__ float red[256];
    float m = -1e30f;
    for (int j = tid; j < NCLS; j += 256) m = fmaxf(m, src[j]);
    red[tid] = m; __syncthreads();
    for (int s = 128; s > 0; s >>= 1) { if (tid < s) red[tid] = fmaxf(red[tid], red[tid + s]); __syncthreads(); }
    m = red[0]; __syncthreads();
    float ssum = 0.f;
    for (int j = tid; j < NCLS; j += 256) ssum += __expf(src[j] - m);
    red[tid] = ssum; __syncthreads();
    for (int s = 128; s > 0; s >>= 1) { if (tid < s) red[tid] += red[tid + s]; __syncthreads(); }
    float inv = 1.f / red[0];
    for (int j = tid; j < NCLS; j += 256) out[b * NCLS + j] = __expf(src[j] - m) * inv;
}

// ---------------- launcher ----------------
extern "C" void kernel_launch(void* const* d_in, const int* in_sizes, int n_in,
                              void* d_out, int out_size) {
    const float* t_lum  = (const float*)d_in[0];
    const float* r_lum  = (const float*)d_in[1];
    const float* r_ab   = (const float*)d_in[2];
    const float* w_rab1 = (const float*)d_in[3];
    const float* b_rab1 = (const float*)d_in[4];
    const float* w_rab2 = (const float*)d_in[5];
    const float* b_rab2 = (const float*)d_in[6];
    const float* w_fa1  = (const float*)d_in[7];
    const float* b_fa1  = (const float*)d_in[8];
    const float* w_fa2  = (const float*)d_in[9];
    const float* b_fa2  = (const float*)d_in[10];
    const float* w_fa3  = (const float*)d_in[11];
    const float* b_fa3  = (const float*)d_in[12];
    const float* w_d1   = (const float*)d_in[13];
    const float* b_d1   = (const float*)d_in[14];
    const float* w_d2   = (const float*)d_in[15];
    const float* b_d2   = (const float*)d_in[16];

    __half *tnh, *tnl, *rnh, *Ahi, *Alo, *fTh;
    float *frab1, *fa, *mpp, *mp, *d1p, *g1, *logits;
    cudaGetSymbolAddress((void**)&tnh,    g_tn_hi);
    cudaGetSymbolAddress((void**)&tnl,    g_tn_lo);
    cudaGetSymbolAddress((void**)&rnh,    g_rn_hi);
    cudaGetSymbolAddress((void**)&Ahi,    g_A_hi);
    cudaGetSymbolAddress((void**)&Alo,    g_A_lo);
    cudaGetSymbolAddress((void**)&fTh,    g_frabT_hi);
    cudaGetSymbolAddress((void**)&frab1,  g_frab1);
    cudaGetSymbolAddress((void**)&fa,     g_fa);
    cudaGetSymbolAddress((void**)&mpp,    g_mpp);
    cudaGetSymbolAddress((void**)&mp,     g_mp);
    cudaGetSymbolAddress((void**)&d1p,    g_d1p);
    cudaGetSymbolAddress((void**)&g1,     g_g1);
    cudaGetSymbolAddress((void**)&logits, g_logits);

    cudaFuncSetAttribute(gemm_nt_mma, cudaFuncAttributeMaxDynamicSharedMemorySize, GEMM_SMEM);
    cudaFuncSetAttribute(gemm_nn_mma, cudaFuncAttributeMaxDynamicSharedMemorySize, GEMM2_SMEM);

    float* out  = (float*)d_out;
    float* Cmat = out + 8000;
    float* s1   = out + 8396608;
    float* s2   = out + 8462144;
    float* s3   = out + 8593216;

    // 1,2: normalize + fp16 split
    normalize_split_hl<<<NB * NN, 256>>>(t_lum, tnh, tnl);
    normalize_split_h<<<NB * NN, 256>>>(r_lum, rnh);

    // 3: cost volume (2 CTAs/SM now)
    gemm_nt_mma<<<dim3(8, 8, NB), 256, GEMM_SMEM>>>(tnh, tnl, rnh, Cmat);

    // 4: softmax -> split-fp16  <- profile slot
    softmax_split_rows<<<NB * NN, 256>>>(Cmat, Ahi, Alo);

    // 5,6: chroma branch
    conv2d_relu_t<16, 1, 2, 1><<<dim3(4, 64, NB), 64, 3 * 18 * 2 * 4>>>(
        r_ab, w_rab1, b_rab1, frab1, 64, 64, 64, 64, 64, 1);
    conv2_t_fp16<<<dim3(4, 32, NB), 128, 3 * 17 * 64 * 4>>>(
        frab1, w_rab2, b_rab2, fTh);

    // 7: attention
    gemm_nn_mma<<<dim3(NN / 64, NB), 256, GEMM2_SMEM>>>(Ahi, Alo, fTh, fa);

    // 8-10: pyramid
    conv2d_relu_t<4, 2, 128, 1><<<dim3(4, 16, NB), 128, 3 * 9 * 128 * 4>>>(
        fa, w_fa1, b_fa1, s3, 32, 32, 16, 16, 128, 0);
    conv2d_relu_t<4, 2, 128, 1><<<dim3(2, 8, NB), 256, 3 * 9 * 128 * 4>>>(
        s3, w_fa2, b_fa2, s2, 16, 16, 8, 8, 256, 0);
    conv2d_relu_t<2, 2, 256, 2><<<dim3(4, 4, NB), 256, 3 * 5 * 256 * 4>>>(
        s2, w_fa3, b_fa3, s1, 8, 8, 4, 4, 512, 0);

    // 11-12: maxpool 2-phase
    maxpool_p1<<<dim3(8, 8, NB), 256>>>(t_lum, mpp);
    maxpool_p2<<<dim3(8, NB), 256>>>(mpp, mp);

    // 13-14: dense1 2-phase
    dense1_p1<<<dim3(8, NB), 512>>>(mp, w_d1, d1p);
    dense1_p2<<<NB, 512>>>(d1p, b_d1, g1);

    // 15-16: dense2 + softmax
    dense2_p1<<<dim3(8, NB), 128>>>(g1, w_d2, b_d2, logits);
    softmax1000<<<NB, 256>>>(logits, out);
}